// round 3
// baseline (speedup 1.0000x reference)
#include <cuda_runtime.h>
#include <stdint.h>
#include <math.h>

// Problem constants
#define B_   4
#define L_   2048
#define D_   1024
#define NH   16
#define DK   64
#define BH_  (B_*NH)     // 64
#define ML_  (B_*L_)     // 8192

// ---------------- scratch (static device arrays; no allocation allowed) ----------
__device__ float g_Qh[(size_t)BH_*L_*DK];                 // [bh][l][dk]
__device__ float g_Kh[(size_t)BH_*L_*DK];
__device__ float g_Vh[(size_t)BH_*L_*DK];
__device__ float g_P [(size_t)B_*L_*NH*L_];               // 1.07 GB  [b][q][h][k]
__device__ float g_X [(size_t)ML_*D_];                    // pre-LN activations

// ---------------- helpers ----------------
__device__ __forceinline__ float blockSum256(float v) {
    __shared__ float s[8];
    #pragma unroll
    for (int o = 16; o; o >>= 1) v += __shfl_xor_sync(0xffffffffu, v, o);
    if ((threadIdx.x & 31) == 0) s[threadIdx.x >> 5] = v;
    __syncthreads();
    if (threadIdx.x < 32) {
        float w = (threadIdx.x < 8) ? s[threadIdx.x] : 0.0f;
        #pragma unroll
        for (int o = 4; o; o >>= 1) w += __shfl_xor_sync(0xffffffffu, w, o);
        if (threadIdx.x == 0) s[0] = w;
    }
    __syncthreads();
    float r = s[0];
    __syncthreads();
    return r;
}

__device__ __forceinline__ float blockMax256(float v) {
    __shared__ float s[8];
    #pragma unroll
    for (int o = 16; o; o >>= 1) v = fmaxf(v, __shfl_xor_sync(0xffffffffu, v, o));
    if ((threadIdx.x & 31) == 0) s[threadIdx.x >> 5] = v;
    __syncthreads();
    if (threadIdx.x < 32) {
        float w = (threadIdx.x < 8) ? s[threadIdx.x] : -3.4e38f;
        #pragma unroll
        for (int o = 4; o; o >>= 1) w = fmaxf(w, __shfl_xor_sync(0xffffffffu, w, o));
        if (threadIdx.x == 0) s[0] = w;
    }
    __syncthreads();
    float r = s[0];
    __syncthreads();
    return r;
}

// FFMA-only exp for x <= 0 (keeps MUFU pipe idle). |rel err| < 3e-6.
__device__ __forceinline__ float fast_exp(float x) {
    x = fmaxf(x, -80.0f);
    float y = x * 1.4426950408889634f;
    float t = y + 12582912.0f;
    int   n = __float_as_int(t) - 0x4B400000;
    float f = y - (t - 12582912.0f);
    float u = f * 0.6931471805599453f;
    float p = 1.0f + u * (1.0f + u * (0.5f + u * (0.166666667f + u * (0.0416666667f + u * 0.008333333f))));
    return p * __int_as_float((n + 127) << 23);
}

// ---------------- merged QKV projection: z selects (Q,Wq,bq)->Qh etc. ----------------
__global__ __launch_bounds__(256) void qkv_gemm(
    const float* __restrict__ Qin, const float* __restrict__ Kin, const float* __restrict__ Vin,
    const float* __restrict__ Wq,  const float* __restrict__ Wk,  const float* __restrict__ Wv,
    const float* __restrict__ bq,  const float* __restrict__ bk,  const float* __restrict__ bv,
    float* __restrict__ Qh, float* __restrict__ Kh, float* __restrict__ Vh)
{
    const float* A    = (blockIdx.z == 0) ? Qin : (blockIdx.z == 1) ? Kin : Vin;
    const float* W    = (blockIdx.z == 0) ? Wq  : (blockIdx.z == 1) ? Wk  : Wv;
    const float* bias = (blockIdx.z == 0) ? bq  : (blockIdx.z == 1) ? bk  : bv;
    float*       C    = (blockIdx.z == 0) ? Qh  : (blockIdx.z == 1) ? Kh  : Vh;
    const int K = D_;

    __shared__ float As[16][128];
    __shared__ float Ws[16][128];
    const int m0 = blockIdx.y * 128;
    const int n0 = blockIdx.x * 128;
    const int t  = threadIdx.x;
    const int ty = t >> 4, tx = t & 15;

    float acc[8][8];
    #pragma unroll
    for (int i = 0; i < 8; i++)
        #pragma unroll
        for (int j = 0; j < 8; j++) acc[i][j] = 0.0f;

    for (int k0 = 0; k0 < K; k0 += 16) {
        #pragma unroll
        for (int it = 0; it < 2; it++) {
            int f   = t + it * 256;
            int row = f >> 2;
            int c4  = (f & 3) * 4;
            float4 a = *reinterpret_cast<const float4*>(&A[(size_t)(m0 + row) * K + k0 + c4]);
            As[c4 + 0][row] = a.x; As[c4 + 1][row] = a.y;
            As[c4 + 2][row] = a.z; As[c4 + 3][row] = a.w;
            float4 b = *reinterpret_cast<const float4*>(&W[(size_t)(n0 + row) * K + k0 + c4]);
            Ws[c4 + 0][row] = b.x; Ws[c4 + 1][row] = b.y;
            Ws[c4 + 2][row] = b.z; Ws[c4 + 3][row] = b.w;
        }
        __syncthreads();
        #pragma unroll
        for (int kk = 0; kk < 16; kk++) {
            float ra[8], rb[8];
            float4 a0 = *reinterpret_cast<float4*>(&As[kk][ty * 8]);
            float4 a1 = *reinterpret_cast<float4*>(&As[kk][ty * 8 + 4]);
            float4 b0 = *reinterpret_cast<float4*>(&Ws[kk][tx * 8]);
            float4 b1 = *reinterpret_cast<float4*>(&Ws[kk][tx * 8 + 4]);
            ra[0]=a0.x; ra[1]=a0.y; ra[2]=a0.z; ra[3]=a0.w;
            ra[4]=a1.x; ra[5]=a1.y; ra[6]=a1.z; ra[7]=a1.w;
            rb[0]=b0.x; rb[1]=b0.y; rb[2]=b0.z; rb[3]=b0.w;
            rb[4]=b1.x; rb[5]=b1.y; rb[6]=b1.z; rb[7]=b1.w;
            #pragma unroll
            for (int i = 0; i < 8; i++)
                #pragma unroll
                for (int j = 0; j < 8; j++)
                    acc[i][j] += ra[i] * rb[j];
        }
        __syncthreads();
    }

    #pragma unroll
    for (int i = 0; i < 8; i++) {
        int m = m0 + ty * 8 + i;
        int b = m >> 11, l = m & (L_ - 1);
        #pragma unroll
        for (int j = 0; j < 8; j++) {
            int n = n0 + tx * 8 + j;
            int h = n >> 6, d = n & (DK - 1);
            C[(((size_t)(b * NH + h)) * L_ + l) * DK + d] = acc[i][j] + bias[n];
        }
    }
}

// ---------------- out-projection + residual (single GEMM) ----------------
__global__ __launch_bounds__(256) void out_gemm(
    const float* __restrict__ A, const float* __restrict__ W,
    const float* __restrict__ bias, const float* __restrict__ R,
    float* __restrict__ C)
{
    const int K = D_, N = D_;
    __shared__ float As[16][128];
    __shared__ float Ws[16][128];
    const int m0 = blockIdx.y * 128;
    const int n0 = blockIdx.x * 128;
    const int t  = threadIdx.x;
    const int ty = t >> 4, tx = t & 15;

    float acc[8][8];
    #pragma unroll
    for (int i = 0; i < 8; i++)
        #pragma unroll
        for (int j = 0; j < 8; j++) acc[i][j] = 0.0f;

    for (int k0 = 0; k0 < K; k0 += 16) {
        #pragma unroll
        for (int it = 0; it < 2; it++) {
            int f   = t + it * 256;
            int row = f >> 2;
            int c4  = (f & 3) * 4;
            float4 a = *reinterpret_cast<const float4*>(&A[(size_t)(m0 + row) * K + k0 + c4]);
            As[c4 + 0][row] = a.x; As[c4 + 1][row] = a.y;
            As[c4 + 2][row] = a.z; As[c4 + 3][row] = a.w;
            float4 b = *reinterpret_cast<const float4*>(&W[(size_t)(n0 + row) * K + k0 + c4]);
            Ws[c4 + 0][row] = b.x; Ws[c4 + 1][row] = b.y;
            Ws[c4 + 2][row] = b.z; Ws[c4 + 3][row] = b.w;
        }
        __syncthreads();
        #pragma unroll
        for (int kk = 0; kk < 16; kk++) {
            float ra[8], rb[8];
            float4 a0 = *reinterpret_cast<float4*>(&As[kk][ty * 8]);
            float4 a1 = *reinterpret_cast<float4*>(&As[kk][ty * 8 + 4]);
            float4 b0 = *reinterpret_cast<float4*>(&Ws[kk][tx * 8]);
            float4 b1 = *reinterpret_cast<float4*>(&Ws[kk][tx * 8 + 4]);
            ra[0]=a0.x; ra[1]=a0.y; ra[2]=a0.z; ra[3]=a0.w;
            ra[4]=a1.x; ra[5]=a1.y; ra[6]=a1.z; ra[7]=a1.w;
            rb[0]=b0.x; rb[1]=b0.y; rb[2]=b0.z; rb[3]=b0.w;
            rb[4]=b1.x; rb[5]=b1.y; rb[6]=b1.z; rb[7]=b1.w;
            #pragma unroll
            for (int i = 0; i < 8; i++)
                #pragma unroll
                for (int j = 0; j < 8; j++)
                    acc[i][j] += ra[i] * rb[j];
        }
        __syncthreads();
    }

    #pragma unroll
    for (int i = 0; i < 8; i++) {
        int m = m0 + ty * 8 + i;
        #pragma unroll
        for (int j = 0; j < 8; j++) {
            int n = n0 + tx * 8 + j;
            size_t idx = (size_t)m * N + n;
            C[idx] = acc[i][j] + bias[n] + R[idx];
        }
    }
}

// ---------------- scores (double-buffered): P[b][q][h][k] ----------------
__global__ __launch_bounds__(256) void scores_kernel(
    const float* __restrict__ Qh, const float* __restrict__ Kh,
    const int* __restrict__ mask, float* __restrict__ P, float scale)
{
    __shared__ float As[2][16][128];
    __shared__ float Bs[2][16][128];
    const int bh = blockIdx.z;
    const int b  = bh >> 4, h = bh & 15;
    const float* Aq = Qh + (size_t)bh * L_ * DK;
    const float* Ak = Kh + (size_t)bh * L_ * DK;
    const int q0 = blockIdx.y * 128;
    const int c0 = blockIdx.x * 128;
    const int t  = threadIdx.x;
    const int ty = t >> 4, tx = t & 15;

    float acc[8][8];
    #pragma unroll
    for (int i = 0; i < 8; i++)
        #pragma unroll
        for (int j = 0; j < 8; j++) acc[i][j] = 0.0f;

    // preload chunk 0
    {
        #pragma unroll
        for (int it = 0; it < 2; it++) {
            int f   = t + it * 256;
            int row = f >> 2;
            int c4  = (f & 3) * 4;
            float4 a = *reinterpret_cast<const float4*>(&Aq[(size_t)(q0 + row) * DK + c4]);
            As[0][c4 + 0][row] = a.x; As[0][c4 + 1][row] = a.y;
            As[0][c4 + 2][row] = a.z; As[0][c4 + 3][row] = a.w;
            float4 bb = *reinterpret_cast<const float4*>(&Ak[(size_t)(c0 + row) * DK + c4]);
            Bs[0][c4 + 0][row] = bb.x; Bs[0][c4 + 1][row] = bb.y;
            Bs[0][c4 + 2][row] = bb.z; Bs[0][c4 + 3][row] = bb.w;
        }
    }
    __syncthreads();

    #pragma unroll
    for (int c = 0; c < 4; c++) {
        if (c < 3) {
            int k0 = (c + 1) * 16;
            int nb = (c + 1) & 1;
            #pragma unroll
            for (int it = 0; it < 2; it++) {
                int f   = t + it * 256;
                int row = f >> 2;
                int c4  = (f & 3) * 4;
                float4 a = *reinterpret_cast<const float4*>(&Aq[(size_t)(q0 + row) * DK + k0 + c4]);
                As[nb][c4 + 0][row] = a.x; As[nb][c4 + 1][row] = a.y;
                As[nb][c4 + 2][row] = a.z; As[nb][c4 + 3][row] = a.w;
                float4 bb = *reinterpret_cast<const float4*>(&Ak[(size_t)(c0 + row) * DK + k0 + c4]);
                Bs[nb][c4 + 0][row] = bb.x; Bs[nb][c4 + 1][row] = bb.y;
                Bs[nb][c4 + 2][row] = bb.z; Bs[nb][c4 + 3][row] = bb.w;
            }
        }
        int cb = c & 1;
        #pragma unroll
        for (int kk = 0; kk < 16; kk++) {
            float ra[8], rb[8];
            float4 a0 = *reinterpret_cast<float4*>(&As[cb][kk][ty * 8]);
            float4 a1 = *reinterpret_cast<float4*>(&As[cb][kk][ty * 8 + 4]);
            float4 b0 = *reinterpret_cast<float4*>(&Bs[cb][kk][tx * 8]);
            float4 b1 = *reinterpret_cast<float4*>(&Bs[cb][kk][tx * 8 + 4]);
            ra[0]=a0.x; ra[1]=a0.y; ra[2]=a0.z; ra[3]=a0.w;
            ra[4]=a1.x; ra[5]=a1.y; ra[6]=a1.z; ra[7]=a1.w;
            rb[0]=b0.x; rb[1]=b0.y; rb[2]=b0.z; rb[3]=b0.w;
            rb[4]=b1.x; rb[5]=b1.y; rb[6]=b1.z; rb[7]=b1.w;
            #pragma unroll
            for (int i = 0; i < 8; i++)
                #pragma unroll
                for (int j = 0; j < 8; j++)
                    acc[i][j] += ra[i] * rb[j];
        }
        __syncthreads();
    }

    #pragma unroll
    for (int i = 0; i < 8; i++) {
        int q = q0 + ty * 8 + i;
        const int* mrow = mask + (size_t)b * L_ * L_ + (size_t)q * L_;
        float* prow = P + (((size_t)(b * L_ + q)) * NH + h) * L_;
        #pragma unroll
        for (int j = 0; j < 8; j += 4) {
            int c = c0 + tx * 8 + j;
            int4 m4 = *reinterpret_cast<const int4*>(&mrow[c]);
            float v0 = acc[i][j + 0] * scale;
            float v1 = acc[i][j + 1] * scale;
            float v2 = acc[i][j + 2] * scale;
            float v3 = acc[i][j + 3] * scale;
            if (m4.x) v0 = -1e9f;
            if (m4.y) v1 = -1e9f;
            if (m4.z) v2 = -1e9f;
            if (m4.w) v3 = -1e9f;
            *reinterpret_cast<float4*>(&prow[c]) = make_float4(v0, v1, v2, v3);
        }
    }
}

// ------- fused softmax (in place) + head mean: one block per (b,q) -------
__global__ __launch_bounds__(256) void softmax_mean_kernel(
    float* __restrict__ P, float* __restrict__ out2)
{
    float* base = P + (size_t)blockIdx.x * NH * L_;   // blockIdx.x = b*L + q
    const int t = threadIdx.x;
    float macc[8];
    #pragma unroll
    for (int i = 0; i < 8; i++) macc[i] = 0.0f;

    for (int h = 0; h < NH; h++) {
        float* p = base + (size_t)h * L_;
        float v[8];
        float mx = -3.4e38f;
        #pragma unroll
        for (int i = 0; i < 8; i++) { v[i] = p[t + i * 256]; mx = fmaxf(mx, v[i]); }
        mx = blockMax256(mx);
        float s = 0.0f;
        #pragma unroll
        for (int i = 0; i < 8; i++) { v[i] = fast_exp(v[i] - mx); s += v[i]; }
        s = blockSum256(s);
        float inv = 1.0f / s;
        #pragma unroll
        for (int i = 0; i < 8; i++) {
            float pv = v[i] * inv;
            p[t + i * 256] = pv;
            macc[i] += pv;
        }
    }
    float* o = out2 + (size_t)blockIdx.x * L_;
    #pragma unroll
    for (int i = 0; i < 8; i++) o[t + i * 256] = macc[i] * (1.0f / NH);
}

// ---- context = P @ Vh (double-buffered), P layout [b][q][h][k], out [B,L,D] ----
__global__ __launch_bounds__(256) void context_kernel(
    const float* __restrict__ P, const float* __restrict__ Vh,
    float* __restrict__ out1)
{
    __shared__ float As[2][16][128];
    __shared__ float Bs[2][16][DK];
    const int bh = blockIdx.z;
    const int b  = bh >> 4, h = bh & 15;
    const float* Bv = Vh + (size_t)bh * L_ * DK;
    const int q0 = blockIdx.y * 128;
    const int t  = threadIdx.x;
    const int ty = t >> 4, tx = t & 15;

    // row pointer helper for P: row q -> P + ((b*L + q)*NH + h)*L
    const size_t prow_stride = (size_t)NH * L_;
    const float* Pbase = P + ((size_t)(b * L_ + q0) * NH + h) * L_;

    float acc[8][4];
    #pragma unroll
    for (int i = 0; i < 8; i++)
        #pragma unroll
        for (int j = 0; j < 4; j++) acc[i][j] = 0.0f;

    // preload chunk 0
    {
        #pragma unroll
        for (int it = 0; it < 2; it++) {
            int f   = t + it * 256;
            int row = f >> 2;
            int c4  = (f & 3) * 4;
            float4 a = *reinterpret_cast<const float4*>(&Pbase[(size_t)row * prow_stride + c4]);
            As[0][c4 + 0][row] = a.x; As[0][c4 + 1][row] = a.y;
            As[0][c4 + 2][row] = a.z; As[0][c4 + 3][row] = a.w;
        }
        int row = t >> 4;
        int c4  = (t & 15) * 4;
        float4 bb = *reinterpret_cast<const float4*>(&Bv[(size_t)row * DK + c4]);
        *reinterpret_cast<float4*>(&Bs[0][row][c4]) = bb;
    }
    __syncthreads();

    for (int c = 0; c < L_ / 16; c++) {
        if (c < L_ / 16 - 1) {
            int k0 = (c + 1) * 16;
            int nb = (c + 1) & 1;
            #pragma unroll
            for (int it = 0; it < 2; it++) {
                int f   = t + it * 256;
                int row = f >> 2;
                int c4  = (f & 3) * 4;
                float4 a = *reinterpret_cast<const float4*>(&Pbase[(size_t)row * prow_stride + k0 + c4]);
                As[nb][c4 + 0][row] = a.x; As[nb][c4 + 1][row] = a.y;
                As[nb][c4 + 2][row] = a.z; As[nb][c4 + 3][row] = a.w;
            }
            int row = t >> 4;
            int c4  = (t & 15) * 4;
            float4 bb = *reinterpret_cast<const float4*>(&Bv[(size_t)(k0 + row) * DK + c4]);
            *reinterpret_cast<float4*>(&Bs[nb][row][c4]) = bb;
        }
        int cb = c & 1;
        #pragma unroll
        for (int kk = 0; kk < 16; kk++) {
            float ra[8], rb[4];
            float4 a0 = *reinterpret_cast<float4*>(&As[cb][kk][ty * 8]);
            float4 a1 = *reinterpret_cast<float4*>(&As[cb][kk][ty * 8 + 4]);
            float4 b0 = *reinterpret_cast<float4*>(&Bs[cb][kk][tx * 4]);
            ra[0]=a0.x; ra[1]=a0.y; ra[2]=a0.z; ra[3]=a0.w;
            ra[4]=a1.x; ra[5]=a1.y; ra[6]=a1.z; ra[7]=a1.w;
            rb[0]=b0.x; rb[1]=b0.y; rb[2]=b0.z; rb[3]=b0.w;
            #pragma unroll
            for (int i = 0; i < 8; i++)
                #pragma unroll
                for (int j = 0; j < 4; j++)
                    acc[i][j] += ra[i] * rb[j];
        }
        __syncthreads();
    }

    #pragma unroll
    for (int i = 0; i < 8; i++) {
        int q = q0 + ty * 8 + i;
        #pragma unroll
        for (int j = 0; j < 4; j++) {
            int d = tx * 4 + j;
            out1[((size_t)(b * L_) + q) * D_ + h * DK + d] = acc[i][j];
        }
    }
}

// ---------------- LayerNorm rows of X -> out0 ----------------
__global__ __launch_bounds__(256) void ln_kernel(
    const float* __restrict__ X, const float* __restrict__ gamma,
    const float* __restrict__ beta, float* __restrict__ out0)
{
    const int m = blockIdx.x;
    const int t = threadIdx.x;
    const float4* x4 = reinterpret_cast<const float4*>(X + (size_t)m * D_);
    float4 v = x4[t];
    float s = v.x + v.y + v.z + v.w;
    s = blockSum256(s);
    float mu = s * (1.0f / D_);
    float dx = v.x - mu, dy = v.y - mu, dz = v.z - mu, dw = v.w - mu;
    float ss = dx * dx + dy * dy + dz * dz + dw * dw;
    ss = blockSum256(ss);
    float r = rsqrtf(ss * (1.0f / D_) + 1e-5f);
    const float4 g  = reinterpret_cast<const float4*>(gamma)[t];
    const float4 be = reinterpret_cast<const float4*>(beta)[t];
    float4 o;
    o.x = dx * r * g.x + be.x;
    o.y = dy * r * g.y + be.y;
    o.z = dz * r * g.z + be.z;
    o.w = dw * r * g.w + be.w;
    reinterpret_cast<float4*>(out0 + (size_t)m * D_)[t] = o;
}

// ---------------- launch ----------------
extern "C" void kernel_launch(void* const* d_in, const int* in_sizes, int n_in,
                              void* d_out, int out_size)
{
    const float* Q     = (const float*)d_in[0];
    const float* K     = (const float*)d_in[1];
    const float* V     = (const float*)d_in[2];
    const int*   mask  = (const int*)d_in[3];
    const float* Wq    = (const float*)d_in[4];
    const float* bq    = (const float*)d_in[5];
    const float* Wk    = (const float*)d_in[6];
    const float* bk    = (const float*)d_in[7];
    const float* Wv    = (const float*)d_in[8];
    const float* bv    = (const float*)d_in[9];
    const float* Wo    = (const float*)d_in[10];
    const float* bo    = (const float*)d_in[11];
    const float* gamma = (const float*)d_in[12];
    const float* beta  = (const float*)d_in[13];

    float* out0 = (float*)d_out;                       // output  [B,L,D]
    float* out1 = out0 + (size_t)ML_ * D_;             // context [B,L,D]
    float* out2 = out1 + (size_t)ML_ * D_;             // attn_mean [B,L,L]

    void *pQh, *pKh, *pVh, *pP, *pX;
    cudaGetSymbolAddress(&pQh, g_Qh);
    cudaGetSymbolAddress(&pKh, g_Kh);
    cudaGetSymbolAddress(&pVh, g_Vh);
    cudaGetSymbolAddress(&pP,  g_P);
    cudaGetSymbolAddress(&pX,  g_X);

    // 1) QKV projections -> head-split scratch (one launch)
    qkv_gemm<<<dim3(8, 64, 3), 256>>>(Q, K, V, Wq, Wk, Wv, bq, bk, bv,
                                      (float*)pQh, (float*)pKh, (float*)pVh);

    // 2) masked, scaled scores -> P[b][q][h][k]
    scores_kernel<<<dim3(16, 16, BH_), 256>>>((const float*)pQh, (const float*)pKh,
                                              mask, (float*)pP, 0.125f);

    // 3) fused softmax (in place) + head mean
    softmax_mean_kernel<<<B_ * L_, 256>>>((float*)pP, out2);

    // 4) context = P @ V  (directly into out1)
    context_kernel<<<dim3(1, 16, BH_), 256>>>((const float*)pP, (const float*)pVh, out1);

    // 5) output projection + bias + residual -> X
    out_gemm<<<dim3(8, 64), 256>>>(out1, Wo, bo, Q, (float*)pX);

    // 6) LayerNorm -> out0
    ln_kernel<<<ML_, 256>>>((const float*)pX, gamma, beta, out0);
}

// round 4
// speedup vs baseline: 2.0705x; 2.0705x over previous
#include <cuda_runtime.h>
#include <stdint.h>
#include <math.h>

// Problem constants
#define B_   4
#define L_   2048
#define D_   1024
#define NH   16
#define DK   64
#define BH_  (B_*NH)     // 64
#define ML_  (B_*L_)     // 8192

// ---------------- scratch (static device arrays; no allocation allowed) ----------
__device__ float g_Qh[(size_t)BH_*L_*DK];                 // [bh][l][dk]
__device__ float g_Kh[(size_t)BH_*L_*DK];                 // [bh][l][dk]
__device__ float g_Vt[(size_t)BH_*DK*L_];                 // [bh][d][l]  (transposed V)
__device__ float g_P [(size_t)B_*L_*NH*L_];               // 1.07 GB  [b][q][h][k]
__device__ float g_X [(size_t)ML_*D_];                    // pre-LN activations

// ---------------- helpers ----------------
__device__ __forceinline__ float blockSum256(float v) {
    __shared__ float s[8];
    #pragma unroll
    for (int o = 16; o; o >>= 1) v += __shfl_xor_sync(0xffffffffu, v, o);
    if ((threadIdx.x & 31) == 0) s[threadIdx.x >> 5] = v;
    __syncthreads();
    if (threadIdx.x < 32) {
        float w = (threadIdx.x < 8) ? s[threadIdx.x] : 0.0f;
        #pragma unroll
        for (int o = 4; o; o >>= 1) w += __shfl_xor_sync(0xffffffffu, w, o);
        if (threadIdx.x == 0) s[0] = w;
    }
    __syncthreads();
    float r = s[0];
    __syncthreads();
    return r;
}

__device__ __forceinline__ float blockMax256(float v) {
    __shared__ float s[8];
    #pragma unroll
    for (int o = 16; o; o >>= 1) v = fmaxf(v, __shfl_xor_sync(0xffffffffu, v, o));
    if ((threadIdx.x & 31) == 0) s[threadIdx.x >> 5] = v;
    __syncthreads();
    if (threadIdx.x < 32) {
        float w = (threadIdx.x < 8) ? s[threadIdx.x] : -3.4e38f;
        #pragma unroll
        for (int o = 4; o; o >>= 1) w = fmaxf(w, __shfl_xor_sync(0xffffffffu, w, o));
        if (threadIdx.x == 0) s[0] = w;
    }
    __syncthreads();
    float r = s[0];
    __syncthreads();
    return r;
}

// FFMA-only exp for x <= 0. |rel err| < 3e-6.
__device__ __forceinline__ float fast_exp(float x) {
    x = fmaxf(x, -80.0f);
    float y = x * 1.4426950408889634f;
    float t = y + 12582912.0f;
    int   n = __float_as_int(t) - 0x4B400000;
    float f = y - (t - 12582912.0f);
    float u = f * 0.6931471805599453f;
    float p = 1.0f + u * (1.0f + u * (0.5f + u * (0.166666667f + u * (0.0416666667f + u * 0.008333333f))));
    return p * __int_as_float((n + 127) << 23);
}

// tf32 round-to-nearest (stays in a 32-bit float container)
__device__ __forceinline__ float tf32f(float x) {
    uint32_t u;
    asm("cvt.rna.tf32.f32 %0, %1;" : "=r"(u) : "f"(x));
    return __uint_as_float(u);
}

// D += A(16x8,row) * B(8x8,col)   tf32 inputs, f32 accum
__device__ __forceinline__ void mma8(float* d, const uint32_t* a, const uint32_t* b) {
    asm volatile(
        "mma.sync.aligned.m16n8k8.row.col.f32.tf32.tf32.f32 "
        "{%0,%1,%2,%3}, {%4,%5,%6,%7}, {%8,%9}, {%0,%1,%2,%3};"
        : "+f"(d[0]), "+f"(d[1]), "+f"(d[2]), "+f"(d[3])
        : "r"(a[0]), "r"(a[1]), "r"(a[2]), "r"(a[3]), "r"(b[0]), "r"(b[1]));
}

// ============ merged QKV projection (tf32 tensor core) ============
// z=0: Qh[bh][l][dk], z=1: Kh[bh][l][dk], z=2: Vt[bh][d][l]
__global__ __launch_bounds__(256) void qkv_gemm(
    const float* __restrict__ Qin, const float* __restrict__ Kin, const float* __restrict__ Vin,
    const float* __restrict__ Wq,  const float* __restrict__ Wk,  const float* __restrict__ Wv,
    const float* __restrict__ bq,  const float* __restrict__ bk,  const float* __restrict__ bv,
    float* __restrict__ Qh, float* __restrict__ Kh, float* __restrict__ Vt)
{
    const int zid = blockIdx.z;
    const float* A    = (zid == 0) ? Qin : (zid == 1) ? Kin : Vin;
    const float* W    = (zid == 0) ? Wq  : (zid == 1) ? Wk  : Wv;
    const float* bias = (zid == 0) ? bq  : (zid == 1) ? bk  : bv;

    __shared__ float As[128][36];
    __shared__ float Bs[128][36];
    const int t = threadIdx.x, lane = t & 31, wid = t >> 5;
    const int wm = wid >> 1, wn = wid & 1;        // 4 x 2 warps, warp tile 32m x 64n
    const int g = lane >> 2, tig = lane & 3;
    const int m0 = blockIdx.y * 128, n0 = blockIdx.x * 128;

    float acc[2][8][4];
    #pragma unroll
    for (int mt = 0; mt < 2; mt++)
        #pragma unroll
        for (int nt = 0; nt < 8; nt++)
            #pragma unroll
            for (int i = 0; i < 4; i++) acc[mt][nt][i] = 0.0f;

    for (int k0 = 0; k0 < D_; k0 += 32) {
        #pragma unroll
        for (int it = 0; it < 4; it++) {
            int r = (t >> 3) + it * 32, c4 = (t & 7) * 4;
            float4 a = *reinterpret_cast<const float4*>(&A[(size_t)(m0 + r) * D_ + k0 + c4]);
            a.x = tf32f(a.x); a.y = tf32f(a.y); a.z = tf32f(a.z); a.w = tf32f(a.w);
            *reinterpret_cast<float4*>(&As[r][c4]) = a;
            float4 w = *reinterpret_cast<const float4*>(&W[(size_t)(n0 + r) * D_ + k0 + c4]);
            w.x = tf32f(w.x); w.y = tf32f(w.y); w.z = tf32f(w.z); w.w = tf32f(w.w);
            *reinterpret_cast<float4*>(&Bs[r][c4]) = w;
        }
        __syncthreads();
        #pragma unroll
        for (int kk = 0; kk < 32; kk += 8) {
            uint32_t af[2][4], bf[8][2];
            #pragma unroll
            for (int mt = 0; mt < 2; mt++) {
                int rm = wm * 32 + mt * 16 + g;
                af[mt][0] = __float_as_uint(As[rm][kk + tig]);
                af[mt][1] = __float_as_uint(As[rm + 8][kk + tig]);
                af[mt][2] = __float_as_uint(As[rm][kk + tig + 4]);
                af[mt][3] = __float_as_uint(As[rm + 8][kk + tig + 4]);
            }
            #pragma unroll
            for (int nt = 0; nt < 8; nt++) {
                int rn = wn * 64 + nt * 8 + g;
                bf[nt][0] = __float_as_uint(Bs[rn][kk + tig]);
                bf[nt][1] = __float_as_uint(Bs[rn][kk + tig + 4]);
            }
            #pragma unroll
            for (int mt = 0; mt < 2; mt++)
                #pragma unroll
                for (int nt = 0; nt < 8; nt++)
                    mma8(acc[mt][nt], af[mt], bf[nt]);
        }
        __syncthreads();
    }

    // epilogue: head-split stores
    #pragma unroll
    for (int mt = 0; mt < 2; mt++) {
        #pragma unroll
        for (int nt = 0; nt < 8; nt++) {
            int n  = n0 + wn * 64 + nt * 8 + tig * 2;
            int h  = n >> 6, d = n & (DK - 1);
            float2 bv2 = *reinterpret_cast<const float2*>(&bias[n]);
            #pragma unroll
            for (int rr = 0; rr < 2; rr++) {
                int m = m0 + wm * 32 + mt * 16 + g + rr * 8;
                int bq_ = m >> 11, l = m & (L_ - 1);
                float v0 = acc[mt][nt][rr * 2 + 0] + bv2.x;
                float v1 = acc[mt][nt][rr * 2 + 1] + bv2.y;
                if (zid < 2) {
                    float* C = (zid == 0) ? Qh : Kh;
                    *reinterpret_cast<float2*>(
                        &C[(((size_t)(bq_ * NH + h)) * L_ + l) * DK + d]) = make_float2(v0, v1);
                } else {
                    size_t base = ((size_t)(bq_ * NH + h) * DK + d) * L_ + l;
                    Vt[base]      = v0;
                    Vt[base + L_] = v1;   // d+1 row
                }
            }
        }
    }
}

// ============ output projection + residual (tf32 tensor core) ============
__global__ __launch_bounds__(256) void out_gemm(
    const float* __restrict__ A, const float* __restrict__ W,
    const float* __restrict__ bias, const float* __restrict__ R,
    float* __restrict__ C)
{
    __shared__ float As[128][36];
    __shared__ float Bs[128][36];
    const int t = threadIdx.x, lane = t & 31, wid = t >> 5;
    const int wm = wid >> 1, wn = wid & 1;
    const int g = lane >> 2, tig = lane & 3;
    const int m0 = blockIdx.y * 128, n0 = blockIdx.x * 128;

    float acc[2][8][4];
    #pragma unroll
    for (int mt = 0; mt < 2; mt++)
        #pragma unroll
        for (int nt = 0; nt < 8; nt++)
            #pragma unroll
            for (int i = 0; i < 4; i++) acc[mt][nt][i] = 0.0f;

    for (int k0 = 0; k0 < D_; k0 += 32) {
        #pragma unroll
        for (int it = 0; it < 4; it++) {
            int r = (t >> 3) + it * 32, c4 = (t & 7) * 4;
            float4 a = *reinterpret_cast<const float4*>(&A[(size_t)(m0 + r) * D_ + k0 + c4]);
            a.x = tf32f(a.x); a.y = tf32f(a.y); a.z = tf32f(a.z); a.w = tf32f(a.w);
            *reinterpret_cast<float4*>(&As[r][c4]) = a;
            float4 w = *reinterpret_cast<const float4*>(&W[(size_t)(n0 + r) * D_ + k0 + c4]);
            w.x = tf32f(w.x); w.y = tf32f(w.y); w.z = tf32f(w.z); w.w = tf32f(w.w);
            *reinterpret_cast<float4*>(&Bs[r][c4]) = w;
        }
        __syncthreads();
        #pragma unroll
        for (int kk = 0; kk < 32; kk += 8) {
            uint32_t af[2][4], bf[8][2];
            #pragma unroll
            for (int mt = 0; mt < 2; mt++) {
                int rm = wm * 32 + mt * 16 + g;
                af[mt][0] = __float_as_uint(As[rm][kk + tig]);
                af[mt][1] = __float_as_uint(As[rm + 8][kk + tig]);
                af[mt][2] = __float_as_uint(As[rm][kk + tig + 4]);
                af[mt][3] = __float_as_uint(As[rm + 8][kk + tig + 4]);
            }
            #pragma unroll
            for (int nt = 0; nt < 8; nt++) {
                int rn = wn * 64 + nt * 8 + g;
                bf[nt][0] = __float_as_uint(Bs[rn][kk + tig]);
                bf[nt][1] = __float_as_uint(Bs[rn][kk + tig + 4]);
            }
            #pragma unroll
            for (int mt = 0; mt < 2; mt++)
                #pragma unroll
                for (int nt = 0; nt < 8; nt++)
                    mma8(acc[mt][nt], af[mt], bf[nt]);
        }
        __syncthreads();
    }

    #pragma unroll
    for (int mt = 0; mt < 2; mt++) {
        #pragma unroll
        for (int nt = 0; nt < 8; nt++) {
            int n = n0 + wn * 64 + nt * 8 + tig * 2;
            float2 bv2 = *reinterpret_cast<const float2*>(&bias[n]);
            #pragma unroll
            for (int rr = 0; rr < 2; rr++) {
                int m = m0 + wm * 32 + mt * 16 + g + rr * 8;
                size_t idx = (size_t)m * D_ + n;
                float2 r2 = *reinterpret_cast<const float2*>(&R[idx]);
                *reinterpret_cast<float2*>(&C[idx]) = make_float2(
                    acc[mt][nt][rr * 2 + 0] + bv2.x + r2.x,
                    acc[mt][nt][rr * 2 + 1] + bv2.y + r2.y);
            }
        }
    }
}

// ============ scores (tf32 tensor core): P[b][q][h][k] ============
__global__ __launch_bounds__(256) void scores_kernel(
    const float* __restrict__ Qh, const float* __restrict__ Kh,
    const int* __restrict__ mask, float* __restrict__ P, float scale)
{
    __shared__ float As[128][36];
    __shared__ float Bs[128][36];
    const int bh = blockIdx.z;
    const int b  = bh >> 4, h = bh & 15;
    const float* Aq = Qh + (size_t)bh * L_ * DK;
    const float* Ak = Kh + (size_t)bh * L_ * DK;
    const int q0 = blockIdx.y * 128;
    const int c0 = blockIdx.x * 128;
    const int t = threadIdx.x, lane = t & 31, wid = t >> 5;
    const int wm = wid >> 1, wn = wid & 1;
    const int g = lane >> 2, tig = lane & 3;

    float acc[2][8][4];
    #pragma unroll
    for (int mt = 0; mt < 2; mt++)
        #pragma unroll
        for (int nt = 0; nt < 8; nt++)
            #pragma unroll
            for (int i = 0; i < 4; i++) acc[mt][nt][i] = 0.0f;

    #pragma unroll
    for (int k0 = 0; k0 < DK; k0 += 32) {
        #pragma unroll
        for (int it = 0; it < 4; it++) {
            int r = (t >> 3) + it * 32, c4 = (t & 7) * 4;
            float4 a = *reinterpret_cast<const float4*>(&Aq[(size_t)(q0 + r) * DK + k0 + c4]);
            a.x = tf32f(a.x); a.y = tf32f(a.y); a.z = tf32f(a.z); a.w = tf32f(a.w);
            *reinterpret_cast<float4*>(&As[r][c4]) = a;
            float4 w = *reinterpret_cast<const float4*>(&Ak[(size_t)(c0 + r) * DK + k0 + c4]);
            w.x = tf32f(w.x); w.y = tf32f(w.y); w.z = tf32f(w.z); w.w = tf32f(w.w);
            *reinterpret_cast<float4*>(&Bs[r][c4]) = w;
        }
        __syncthreads();
        #pragma unroll
        for (int kk = 0; kk < 32; kk += 8) {
            uint32_t af[2][4], bf[8][2];
            #pragma unroll
            for (int mt = 0; mt < 2; mt++) {
                int rm = wm * 32 + mt * 16 + g;
                af[mt][0] = __float_as_uint(As[rm][kk + tig]);
                af[mt][1] = __float_as_uint(As[rm + 8][kk + tig]);
                af[mt][2] = __float_as_uint(As[rm][kk + tig + 4]);
                af[mt][3] = __float_as_uint(As[rm + 8][kk + tig + 4]);
            }
            #pragma unroll
            for (int nt = 0; nt < 8; nt++) {
                int rn = wn * 64 + nt * 8 + g;
                bf[nt][0] = __float_as_uint(Bs[rn][kk + tig]);
                bf[nt][1] = __float_as_uint(Bs[rn][kk + tig + 4]);
            }
            #pragma unroll
            for (int mt = 0; mt < 2; mt++)
                #pragma unroll
                for (int nt = 0; nt < 8; nt++)
                    mma8(acc[mt][nt], af[mt], bf[nt]);
        }
        __syncthreads();
    }

    #pragma unroll
    for (int mt = 0; mt < 2; mt++) {
        #pragma unroll
        for (int nt = 0; nt < 8; nt++) {
            int c = c0 + wn * 64 + nt * 8 + tig * 2;
            #pragma unroll
            for (int rr = 0; rr < 2; rr++) {
                int q = q0 + wm * 32 + mt * 16 + g + rr * 8;
                const int* mrow = mask + (size_t)b * L_ * L_ + (size_t)q * L_;
                int2 m2 = *reinterpret_cast<const int2*>(&mrow[c]);
                float v0 = acc[mt][nt][rr * 2 + 0] * scale;
                float v1 = acc[mt][nt][rr * 2 + 1] * scale;
                if (m2.x) v0 = -1e9f;
                if (m2.y) v1 = -1e9f;
                float* prow = P + (((size_t)(b * L_ + q)) * NH + h) * L_;
                *reinterpret_cast<float2*>(&prow[c]) = make_float2(v0, v1);
            }
        }
    }
}

// ------- fused softmax (in place) + head mean: one block per (b,q) -------
__global__ __launch_bounds__(256) void softmax_mean_kernel(
    float* __restrict__ P, float* __restrict__ out2)
{
    float* base = P + (size_t)blockIdx.x * NH * L_;   // blockIdx.x = b*L + q
    const int t = threadIdx.x;
    float macc[8];
    #pragma unroll
    for (int i = 0; i < 8; i++) macc[i] = 0.0f;

    for (int h = 0; h < NH; h++) {
        float* p = base + (size_t)h * L_;
        float v[8];
        float mx = -3.4e38f;
        #pragma unroll
        for (int i = 0; i < 8; i++) { v[i] = p[t + i * 256]; mx = fmaxf(mx, v[i]); }
        mx = blockMax256(mx);
        float s = 0.0f;
        #pragma unroll
        for (int i = 0; i < 8; i++) { v[i] = fast_exp(v[i] - mx); s += v[i]; }
        s = blockSum256(s);
        float inv = 1.0f / s;
        #pragma unroll
        for (int i = 0; i < 8; i++) {
            float pv = v[i] * inv;
            p[t + i * 256] = pv;
            macc[i] += pv;
        }
    }
    float* o = out2 + (size_t)blockIdx.x * L_;
    #pragma unroll
    for (int i = 0; i < 8; i++) o[t + i * 256] = macc[i] * (1.0f / NH);
}

// ===== context: D[d][q] = Vt(64 x K) . P^T  via  A=Vt rows(d), B=P rows(q) =====
// block: 64(d) x 128(q) per bh-qtile; smem-bounce transpose for coalesced out
__global__ __launch_bounds__(256) void context_kernel(
    const float* __restrict__ P, const float* __restrict__ Vt,
    float* __restrict__ out1)
{
    __shared__ float buf[128 * 68];                      // 34.8 KB, reused
    float (*As)[36] = reinterpret_cast<float(*)[36]>(buf);            // 64 x 36
    float (*Bs)[36] = reinterpret_cast<float(*)[36]>(buf + 64 * 36);  // 128 x 36
    float (*Ss)[68] = reinterpret_cast<float(*)[68]>(buf);            // 128 x 68 (after)

    const int bh = blockIdx.z;
    const int b  = bh >> 4, h = bh & 15;
    const int q0 = blockIdx.x * 128;
    const int t = threadIdx.x, lane = t & 31, wid = t >> 5;
    const int wm = wid >> 2, wn = wid & 3;      // 2(m=d) x 4(n=q) warps, warp 32x32
    const int g = lane >> 2, tig = lane & 3;

    const float* Abase = Vt + (size_t)bh * DK * L_;                         // row d, stride L_
    const float* Bbase = P + ((size_t)(b * L_ + q0) * NH + h) * L_;         // row q, stride NH*L_
    const size_t bstride = (size_t)NH * L_;

    float acc[2][4][4];
    #pragma unroll
    for (int mt = 0; mt < 2; mt++)
        #pragma unroll
        for (int nt = 0; nt < 4; nt++)
            #pragma unroll
            for (int i = 0; i < 4; i++) acc[mt][nt][i] = 0.0f;

    for (int k0 = 0; k0 < L_; k0 += 32) {
        #pragma unroll
        for (int it = 0; it < 2; it++) {
            int r = (t >> 3) + it * 32, c4 = (t & 7) * 4;
            float4 a = *reinterpret_cast<const float4*>(&Abase[(size_t)r * L_ + k0 + c4]);
            a.x = tf32f(a.x); a.y = tf32f(a.y); a.z = tf32f(a.z); a.w = tf32f(a.w);
            *reinterpret_cast<float4*>(&As[r][c4]) = a;
        }
        #pragma unroll
        for (int it = 0; it < 4; it++) {
            int r = (t >> 3) + it * 32, c4 = (t & 7) * 4;
            float4 p4 = *reinterpret_cast<const float4*>(&Bbase[(size_t)r * bstride + k0 + c4]);
            p4.x = tf32f(p4.x); p4.y = tf32f(p4.y); p4.z = tf32f(p4.z); p4.w = tf32f(p4.w);
            *reinterpret_cast<float4*>(&Bs[r][c4]) = p4;
        }
        __syncthreads();
        #pragma unroll
        for (int kk = 0; kk < 32; kk += 8) {
            uint32_t af[2][4], bf[4][2];
            #pragma unroll
            for (int mt = 0; mt < 2; mt++) {
                int rm = wm * 32 + mt * 16 + g;
                af[mt][0] = __float_as_uint(As[rm][kk + tig]);
                af[mt][1] = __float_as_uint(As[rm + 8][kk + tig]);
                af[mt][2] = __float_as_uint(As[rm][kk + tig + 4]);
                af[mt][3] = __float_as_uint(As[rm + 8][kk + tig + 4]);
            }
            #pragma unroll
            for (int nt = 0; nt < 4; nt++) {
                int rn = wn * 32 + nt * 8 + g;
                bf[nt][0] = __float_as_uint(Bs[rn][kk + tig]);
                bf[nt][1] = __float_as_uint(Bs[rn][kk + tig + 4]);
            }
            #pragma unroll
            for (int mt = 0; mt < 2; mt++)
                #pragma unroll
                for (int nt = 0; nt < 4; nt++)
                    mma8(acc[mt][nt], af[mt], bf[nt]);
        }
        __syncthreads();
    }

    // transpose through smem: Ss[q][d], then coalesced store
    #pragma unroll
    for (int mt = 0; mt < 2; mt++) {
        #pragma unroll
        for (int nt = 0; nt < 4; nt++) {
            int d0 = wm * 32 + mt * 16 + g;
            int qq = wn * 32 + nt * 8 + tig * 2;
            Ss[qq][d0]         = acc[mt][nt][0];
            Ss[qq + 1][d0]     = acc[mt][nt][1];
            Ss[qq][d0 + 8]     = acc[mt][nt][2];
            Ss[qq + 1][d0 + 8] = acc[mt][nt][3];
        }
    }
    __syncthreads();

    {
        int qq = t >> 1;
        int d0 = (t & 1) * 32;
        float* orow = out1 + ((size_t)(b * L_) + q0 + qq) * D_ + h * DK + d0;
        #pragma unroll
        for (int j = 0; j < 8; j++) {
            *reinterpret_cast<float4*>(&orow[j * 4]) =
                *reinterpret_cast<float4*>(&Ss[qq][d0 + j * 4]);
        }
    }
}

// ---------------- LayerNorm rows of X -> out0 ----------------
__global__ __launch_bounds__(256) void ln_kernel(
    const float* __restrict__ X, const float* __restrict__ gamma,
    const float* __restrict__ beta, float* __restrict__ out0)
{
    const int m = blockIdx.x;
    const int t = threadIdx.x;
    const float4* x4 = reinterpret_cast<const float4*>(X + (size_t)m * D_);
    float4 v = x4[t];
    float s = v.x + v.y + v.z + v.w;
    s = blockSum256(s);
    float mu = s * (1.0f / D_);
    float dx = v.x - mu, dy = v.y - mu, dz = v.z - mu, dw = v.w - mu;
    float ss = dx * dx + dy * dy + dz * dz + dw * dw;
    ss = blockSum256(ss);
    float r = rsqrtf(ss * (1.0f / D_) + 1e-5f);
    const float4 g  = reinterpret_cast<const float4*>(gamma)[t];
    const float4 be = reinterpret_cast<const float4*>(beta)[t];
    float4 o;
    o.x = dx * r * g.x + be.x;
    o.y = dy * r * g.y + be.y;
    o.z = dz * r * g.z + be.z;
    o.w = dw * r * g.w + be.w;
    reinterpret_cast<float4*>(out0 + (size_t)m * D_)[t] = o;
}

// ---------------- launch ----------------
extern "C" void kernel_launch(void* const* d_in, const int* in_sizes, int n_in,
                              void* d_out, int out_size)
{
    const float* Q     = (const float*)d_in[0];
    const float* K     = (const float*)d_in[1];
    const float* V     = (const float*)d_in[2];
    const int*   mask  = (const int*)d_in[3];
    const float* Wq    = (const float*)d_in[4];
    const float* bq    = (const float*)d_in[5];
    const float* Wk    = (const float*)d_in[6];
    const float* bk    = (const float*)d_in[7];
    const float* Wv    = (const float*)d_in[8];
    const float* bv    = (const float*)d_in[9];
    const float* Wo    = (const float*)d_in[10];
    const float* bo    = (const float*)d_in[11];
    const float* gamma = (const float*)d_in[12];
    const float* beta  = (const float*)d_in[13];

    float* out0 = (float*)d_out;                       // output  [B,L,D]
    float* out1 = out0 + (size_t)ML_ * D_;             // context [B,L,D]
    float* out2 = out1 + (size_t)ML_ * D_;             // attn_mean [B,L,L]

    void *pQh, *pKh, *pVt, *pP, *pX;
    cudaGetSymbolAddress(&pQh, g_Qh);
    cudaGetSymbolAddress(&pKh, g_Kh);
    cudaGetSymbolAddress(&pVt, g_Vt);
    cudaGetSymbolAddress(&pP,  g_P);
    cudaGetSymbolAddress(&pX,  g_X);

    // 1) QKV projections (tensor core) -> head-split scratch; V transposed
    qkv_gemm<<<dim3(8, 64, 3), 256>>>(Q, K, V, Wq, Wk, Wv, bq, bk, bv,
                                      (float*)pQh, (float*)pKh, (float*)pVt);

    // 2) masked, scaled scores (tensor core) -> P[b][q][h][k]
    scores_kernel<<<dim3(16, 16, BH_), 256>>>((const float*)pQh, (const float*)pKh,
                                              mask, (float*)pP, 0.125f);

    // 3) fused softmax (in place) + head mean
    softmax_mean_kernel<<<B_ * L_, 256>>>((float*)pP, out2);

    // 4) context = P @ V (tensor core, V as M-operand) -> out1
    context_kernel<<<dim3(16, 1, BH_), 256>>>((const float*)pP, (const float*)pVt, out1);

    // 5) output projection + bias + residual -> X
    out_gemm<<<dim3(8, 64), 256>>>(out1, Wo, bo, Q, (float*)pX);

    // 6) LayerNorm -> out0
    ln_kernel<<<ML_, 256>>>((const float*)pX, gamma, beta, out0);
}

// round 6
// speedup vs baseline: 2.0921x; 1.0104x over previous
#include <cuda_runtime.h>
#include <stdint.h>
#include <math.h>

// Problem constants
#define B_   4
#define L_   2048
#define D_   1024
#define NH   16
#define DK   64
#define BH_  (B_*NH)     // 64
#define ML_  (B_*L_)     // 8192

// ---------------- scratch (static device arrays; no allocation allowed) ----------
__device__ float g_Qh[(size_t)BH_*L_*DK];                 // [bh][l][dk]
__device__ float g_Kh[(size_t)BH_*L_*DK];                 // [bh][l][dk]
__device__ float g_Vt[(size_t)BH_*DK*L_];                 // [bh][d][l]  (transposed V)
__device__ float g_P [(size_t)B_*L_*NH*L_];               // 1.07 GB raw masked scores [b][q][h][k]
__device__ float g_PS[(size_t)BH_*L_*16*2];               // partial stats [bh][q][tile16][max,sumexp]
__device__ float g_ST[(size_t)BH_*L_*2];                  // final stats [bh][q][M, 1/Z]
__device__ float g_X [(size_t)ML_*D_];                    // pre-LN activations

// ---------------- helpers ----------------
__device__ __forceinline__ float blockSum256(float v) {
    __shared__ float s[8];
    #pragma unroll
    for (int o = 16; o; o >>= 1) v += __shfl_xor_sync(0xffffffffu, v, o);
    if ((threadIdx.x & 31) == 0) s[threadIdx.x >> 5] = v;
    __syncthreads();
    if (threadIdx.x < 32) {
        float w = (threadIdx.x < 8) ? s[threadIdx.x] : 0.0f;
        #pragma unroll
        for (int o = 4; o; o >>= 1) w += __shfl_xor_sync(0xffffffffu, w, o);
        if (threadIdx.x == 0) s[0] = w;
    }
    __syncthreads();
    float r = s[0];
    __syncthreads();
    return r;
}

// FFMA-only exp for x <= 0. |rel err| < 3e-6.
__device__ __forceinline__ float fast_exp(float x) {
    x = fmaxf(x, -80.0f);
    float y = x * 1.4426950408889634f;
    float t = y + 12582912.0f;
    int   n = __float_as_int(t) - 0x4B400000;
    float f = y - (t - 12582912.0f);
    float u = f * 0.6931471805599453f;
    float p = 1.0f + u * (1.0f + u * (0.5f + u * (0.166666667f + u * (0.0416666667f + u * 0.008333333f))));
    return p * __int_as_float((n + 127) << 23);
}

// tf32 round-to-nearest (stays in a 32-bit float container)
__device__ __forceinline__ float tf32f(float x) {
    uint32_t u;
    asm("cvt.rna.tf32.f32 %0, %1;" : "=r"(u) : "f"(x));
    return __uint_as_float(u);
}

// D += A(16x8,row) * B(8x8,col)   tf32 inputs, f32 accum
__device__ __forceinline__ void mma8(float* d, const uint32_t* a, const uint32_t* b) {
    asm volatile(
        "mma.sync.aligned.m16n8k8.row.col.f32.tf32.tf32.f32 "
        "{%0,%1,%2,%3}, {%4,%5,%6,%7}, {%8,%9}, {%0,%1,%2,%3};"
        : "+f"(d[0]), "+f"(d[1]), "+f"(d[2]), "+f"(d[3])
        : "r"(a[0]), "r"(a[1]), "r"(a[2]), "r"(a[3]), "r"(b[0]), "r"(b[1]));
}

// ============ merged QKV projection (tf32 tensor core) ============
__global__ __launch_bounds__(256) void qkv_gemm(
    const float* __restrict__ Qin, const float* __restrict__ Kin, const float* __restrict__ Vin,
    const float* __restrict__ Wq,  const float* __restrict__ Wk,  const float* __restrict__ Wv,
    const float* __restrict__ bq,  const float* __restrict__ bk,  const float* __restrict__ bv,
    float* __restrict__ Qh, float* __restrict__ Kh, float* __restrict__ Vt)
{
    const int zid = blockIdx.z;
    const float* A    = (zid == 0) ? Qin : (zid == 1) ? Kin : Vin;
    const float* W    = (zid == 0) ? Wq  : (zid == 1) ? Wk  : Wv;
    const float* bias = (zid == 0) ? bq  : (zid == 1) ? bk  : bv;

    __shared__ float As[128][36];
    __shared__ float Bs[128][36];
    const int t = threadIdx.x, lane = t & 31, wid = t >> 5;
    const int wm = wid >> 1, wn = wid & 1;
    const int g = lane >> 2, tig = lane & 3;
    const int m0 = blockIdx.y * 128, n0 = blockIdx.x * 128;

    float acc[2][8][4];
    #pragma unroll
    for (int mt = 0; mt < 2; mt++)
        #pragma unroll
        for (int nt = 0; nt < 8; nt++)
            #pragma unroll
            for (int i = 0; i < 4; i++) acc[mt][nt][i] = 0.0f;

    for (int k0 = 0; k0 < D_; k0 += 32) {
        #pragma unroll
        for (int it = 0; it < 4; it++) {
            int r = (t >> 3) + it * 32, c4 = (t & 7) * 4;
            float4 a = *reinterpret_cast<const float4*>(&A[(size_t)(m0 + r) * D_ + k0 + c4]);
            a.x = tf32f(a.x); a.y = tf32f(a.y); a.z = tf32f(a.z); a.w = tf32f(a.w);
            *reinterpret_cast<float4*>(&As[r][c4]) = a;
            float4 w = *reinterpret_cast<const float4*>(&W[(size_t)(n0 + r) * D_ + k0 + c4]);
            w.x = tf32f(w.x); w.y = tf32f(w.y); w.z = tf32f(w.z); w.w = tf32f(w.w);
            *reinterpret_cast<float4*>(&Bs[r][c4]) = w;
        }
        __syncthreads();
        #pragma unroll
        for (int kk = 0; kk < 32; kk += 8) {
            uint32_t af[2][4], bf[8][2];
            #pragma unroll
            for (int mt = 0; mt < 2; mt++) {
                int rm = wm * 32 + mt * 16 + g;
                af[mt][0] = __float_as_uint(As[rm][kk + tig]);
                af[mt][1] = __float_as_uint(As[rm + 8][kk + tig]);
                af[mt][2] = __float_as_uint(As[rm][kk + tig + 4]);
                af[mt][3] = __float_as_uint(As[rm + 8][kk + tig + 4]);
            }
            #pragma unroll
            for (int nt = 0; nt < 8; nt++) {
                int rn = wn * 64 + nt * 8 + g;
                bf[nt][0] = __float_as_uint(Bs[rn][kk + tig]);
                bf[nt][1] = __float_as_uint(Bs[rn][kk + tig + 4]);
            }
            #pragma unroll
            for (int mt = 0; mt < 2; mt++)
                #pragma unroll
                for (int nt = 0; nt < 8; nt++)
                    mma8(acc[mt][nt], af[mt], bf[nt]);
        }
        __syncthreads();
    }

    #pragma unroll
    for (int mt = 0; mt < 2; mt++) {
        #pragma unroll
        for (int nt = 0; nt < 8; nt++) {
            int n  = n0 + wn * 64 + nt * 8 + tig * 2;
            int h  = n >> 6, d = n & (DK - 1);
            float2 bv2 = *reinterpret_cast<const float2*>(&bias[n]);
            #pragma unroll
            for (int rr = 0; rr < 2; rr++) {
                int m = m0 + wm * 32 + mt * 16 + g + rr * 8;
                int bq_ = m >> 11, l = m & (L_ - 1);
                float v0 = acc[mt][nt][rr * 2 + 0] + bv2.x;
                float v1 = acc[mt][nt][rr * 2 + 1] + bv2.y;
                if (zid < 2) {
                    float* C = (zid == 0) ? Qh : Kh;
                    *reinterpret_cast<float2*>(
                        &C[(((size_t)(bq_ * NH + h)) * L_ + l) * DK + d]) = make_float2(v0, v1);
                } else {
                    size_t base = ((size_t)(bq_ * NH + h) * DK + d) * L_ + l;
                    Vt[base]      = v0;
                    Vt[base + L_] = v1;
                }
            }
        }
    }
}

// ============ output projection + residual (tf32 tensor core) ============
__global__ __launch_bounds__(256) void out_gemm(
    const float* __restrict__ A, const float* __restrict__ W,
    const float* __restrict__ bias, const float* __restrict__ R,
    float* __restrict__ C)
{
    __shared__ float As[128][36];
    __shared__ float Bs[128][36];
    const int t = threadIdx.x, lane = t & 31, wid = t >> 5;
    const int wm = wid >> 1, wn = wid & 1;
    const int g = lane >> 2, tig = lane & 3;
    const int m0 = blockIdx.y * 128, n0 = blockIdx.x * 128;

    float acc[2][8][4];
    #pragma unroll
    for (int mt = 0; mt < 2; mt++)
        #pragma unroll
        for (int nt = 0; nt < 8; nt++)
            #pragma unroll
            for (int i = 0; i < 4; i++) acc[mt][nt][i] = 0.0f;

    for (int k0 = 0; k0 < D_; k0 += 32) {
        #pragma unroll
        for (int it = 0; it < 4; it++) {
            int r = (t >> 3) + it * 32, c4 = (t & 7) * 4;
            float4 a = *reinterpret_cast<const float4*>(&A[(size_t)(m0 + r) * D_ + k0 + c4]);
            a.x = tf32f(a.x); a.y = tf32f(a.y); a.z = tf32f(a.z); a.w = tf32f(a.w);
            *reinterpret_cast<float4*>(&As[r][c4]) = a;
            float4 w = *reinterpret_cast<const float4*>(&W[(size_t)(n0 + r) * D_ + k0 + c4]);
            w.x = tf32f(w.x); w.y = tf32f(w.y); w.z = tf32f(w.z); w.w = tf32f(w.w);
            *reinterpret_cast<float4*>(&Bs[r][c4]) = w;
        }
        __syncthreads();
        #pragma unroll
        for (int kk = 0; kk < 32; kk += 8) {
            uint32_t af[2][4], bf[8][2];
            #pragma unroll
            for (int mt = 0; mt < 2; mt++) {
                int rm = wm * 32 + mt * 16 + g;
                af[mt][0] = __float_as_uint(As[rm][kk + tig]);
                af[mt][1] = __float_as_uint(As[rm + 8][kk + tig]);
                af[mt][2] = __float_as_uint(As[rm][kk + tig + 4]);
                af[mt][3] = __float_as_uint(As[rm + 8][kk + tig + 4]);
            }
            #pragma unroll
            for (int nt = 0; nt < 8; nt++) {
                int rn = wn * 64 + nt * 8 + g;
                bf[nt][0] = __float_as_uint(Bs[rn][kk + tig]);
                bf[nt][1] = __float_as_uint(Bs[rn][kk + tig + 4]);
            }
            #pragma unroll
            for (int mt = 0; mt < 2; mt++)
                #pragma unroll
                for (int nt = 0; nt < 8; nt++)
                    mma8(acc[mt][nt], af[mt], bf[nt]);
        }
        __syncthreads();
    }

    #pragma unroll
    for (int mt = 0; mt < 2; mt++) {
        #pragma unroll
        for (int nt = 0; nt < 8; nt++) {
            int n = n0 + wn * 64 + nt * 8 + tig * 2;
            float2 bv2 = *reinterpret_cast<const float2*>(&bias[n]);
            #pragma unroll
            for (int rr = 0; rr < 2; rr++) {
                int m = m0 + wm * 32 + mt * 16 + g + rr * 8;
                size_t idx = (size_t)m * D_ + n;
                float2 r2 = *reinterpret_cast<const float2*>(&R[idx]);
                *reinterpret_cast<float2*>(&C[idx]) = make_float2(
                    acc[mt][nt][rr * 2 + 0] + bv2.x + r2.x,
                    acc[mt][nt][rr * 2 + 1] + bv2.y + r2.y);
            }
        }
    }
}

// ============ scores (tf32) + per-tile softmax partial stats ============
// writes raw masked scores to P[b][q][h][k] and (max, sumexp) per (row, 128-col tile)
__global__ __launch_bounds__(256) void scores_kernel(
    const float* __restrict__ Qh, const float* __restrict__ Kh,
    const int* __restrict__ mask, float* __restrict__ P,
    float* __restrict__ pstats, float scale)
{
    __shared__ float As[128][36];
    __shared__ float Bs[128][36];
    __shared__ float rmax[128][2];
    __shared__ float rsum[128][2];
    const int bh = blockIdx.z;
    const int b  = bh >> 4, h = bh & 15;
    const float* Aq = Qh + (size_t)bh * L_ * DK;
    const float* Ak = Kh + (size_t)bh * L_ * DK;
    const int q0 = blockIdx.y * 128;
    const int c0 = blockIdx.x * 128;
    const int t = threadIdx.x, lane = t & 31, wid = t >> 5;
    const int wm = wid >> 1, wn = wid & 1;
    const int g = lane >> 2, tig = lane & 3;

    float acc[2][8][4];
    #pragma unroll
    for (int mt = 0; mt < 2; mt++)
        #pragma unroll
        for (int nt = 0; nt < 8; nt++)
            #pragma unroll
            for (int i = 0; i < 4; i++) acc[mt][nt][i] = 0.0f;

    #pragma unroll
    for (int k0 = 0; k0 < DK; k0 += 32) {
        #pragma unroll
        for (int it = 0; it < 4; it++) {
            int r = (t >> 3) + it * 32, c4 = (t & 7) * 4;
            float4 a = *reinterpret_cast<const float4*>(&Aq[(size_t)(q0 + r) * DK + k0 + c4]);
            a.x = tf32f(a.x); a.y = tf32f(a.y); a.z = tf32f(a.z); a.w = tf32f(a.w);
            *reinterpret_cast<float4*>(&As[r][c4]) = a;
            float4 w = *reinterpret_cast<const float4*>(&Ak[(size_t)(c0 + r) * DK + k0 + c4]);
            w.x = tf32f(w.x); w.y = tf32f(w.y); w.z = tf32f(w.z); w.w = tf32f(w.w);
            *reinterpret_cast<float4*>(&Bs[r][c4]) = w;
        }
        __syncthreads();
        #pragma unroll
        for (int kk = 0; kk < 32; kk += 8) {
            uint32_t af[2][4], bf[8][2];
            #pragma unroll
            for (int mt = 0; mt < 2; mt++) {
                int rm = wm * 32 + mt * 16 + g;
                af[mt][0] = __float_as_uint(As[rm][kk + tig]);
                af[mt][1] = __float_as_uint(As[rm + 8][kk + tig]);
                af[mt][2] = __float_as_uint(As[rm][kk + tig + 4]);
                af[mt][3] = __float_as_uint(As[rm + 8][kk + tig + 4]);
            }
            #pragma unroll
            for (int nt = 0; nt < 8; nt++) {
                int rn = wn * 64 + nt * 8 + g;
                bf[nt][0] = __float_as_uint(Bs[rn][kk + tig]);
                bf[nt][1] = __float_as_uint(Bs[rn][kk + tig + 4]);
            }
            #pragma unroll
            for (int mt = 0; mt < 2; mt++)
                #pragma unroll
                for (int nt = 0; nt < 8; nt++)
                    mma8(acc[mt][nt], af[mt], bf[nt]);
        }
        __syncthreads();
    }

    // scale + mask in-register, write raw P
    #pragma unroll
    for (int mt = 0; mt < 2; mt++) {
        #pragma unroll
        for (int nt = 0; nt < 8; nt++) {
            int c = c0 + wn * 64 + nt * 8 + tig * 2;
            #pragma unroll
            for (int rr = 0; rr < 2; rr++) {
                int q = q0 + wm * 32 + mt * 16 + g + rr * 8;
                const int* mrow = mask + (size_t)b * L_ * L_ + (size_t)q * L_;
                int2 m2 = *reinterpret_cast<const int2*>(&mrow[c]);
                float v0 = acc[mt][nt][rr * 2 + 0] * scale;
                float v1 = acc[mt][nt][rr * 2 + 1] * scale;
                if (m2.x) v0 = -1e9f;
                if (m2.y) v1 = -1e9f;
                acc[mt][nt][rr * 2 + 0] = v0;
                acc[mt][nt][rr * 2 + 1] = v1;
                float* prow = P + (((size_t)(b * L_ + q)) * NH + h) * L_;
                *reinterpret_cast<float2*>(&prow[c]) = make_float2(v0, v1);
            }
        }
    }

    // phase 1: per-row tile max (this block's 128 cols)
    #pragma unroll
    for (int mt = 0; mt < 2; mt++) {
        #pragma unroll
        for (int rr = 0; rr < 2; rr++) {
            float m = -3.4e38f;
            #pragma unroll
            for (int nt = 0; nt < 8; nt++) {
                m = fmaxf(m, acc[mt][nt][rr * 2 + 0]);
                m = fmaxf(m, acc[mt][nt][rr * 2 + 1]);
            }
            m = fmaxf(m, __shfl_xor_sync(0xffffffffu, m, 1));
            m = fmaxf(m, __shfl_xor_sync(0xffffffffu, m, 2));
            int rl = wm * 32 + mt * 16 + g + rr * 8;
            if (tig == 0) rmax[rl][wn] = m;
        }
    }
    __syncthreads();

    // phase 2: per-row tile sumexp with tile max
    #pragma unroll
    for (int mt = 0; mt < 2; mt++) {
        #pragma unroll
        for (int rr = 0; rr < 2; rr++) {
            int rl = wm * 32 + mt * 16 + g + rr * 8;
            float M = fmaxf(rmax[rl][0], rmax[rl][1]);
            float s = 0.0f;
            #pragma unroll
            for (int nt = 0; nt < 8; nt++) {
                s += fast_exp(acc[mt][nt][rr * 2 + 0] - M);
                s += fast_exp(acc[mt][nt][rr * 2 + 1] - M);
            }
            s += __shfl_xor_sync(0xffffffffu, s, 1);
            s += __shfl_xor_sync(0xffffffffu, s, 2);
            if (tig == 0) rsum[rl][wn] = s;
        }
    }
    __syncthreads();

    // phase 3: one writer per row
    if (wn == 0 && tig == 0) {
        #pragma unroll
        for (int mt = 0; mt < 2; mt++) {
            #pragma unroll
            for (int rr = 0; rr < 2; rr++) {
                int rl = wm * 32 + mt * 16 + g + rr * 8;
                int q = q0 + rl;
                float M = fmaxf(rmax[rl][0], rmax[rl][1]);
                float S = rsum[rl][0] + rsum[rl][1];
                size_t si = (((size_t)bh * L_ + q) * 16 + blockIdx.x) * 2;
                *reinterpret_cast<float2*>(&pstats[si]) = make_float2(M, S);
            }
        }
    }
}

// ============ reduce partial stats -> per-row (M, 1/Z) ============
__global__ __launch_bounds__(256) void stats_reduce(
    const float* __restrict__ pstats, float* __restrict__ st)
{
    int idx = blockIdx.x * 256 + threadIdx.x;     // bh*L + q, total 131072
    const float4* p = reinterpret_cast<const float4*>(pstats + (size_t)idx * 32);
    float mx[16], sm[16];
    #pragma unroll
    for (int i = 0; i < 8; i++) {
        float4 v = p[i];
        mx[i * 2] = v.x; sm[i * 2] = v.y;
        mx[i * 2 + 1] = v.z; sm[i * 2 + 1] = v.w;
    }
    float M = -3.4e38f;
    #pragma unroll
    for (int i = 0; i < 16; i++) M = fmaxf(M, mx[i]);
    float Z = 0.0f;
    #pragma unroll
    for (int i = 0; i < 16; i++) Z += sm[i] * fast_exp(mx[i] - M);
    *reinterpret_cast<float2*>(&st[(size_t)idx * 2]) = make_float2(M, 1.0f / Z);
}

// ============ attn_mean from raw P + stats ============
__global__ __launch_bounds__(256) void mean_kernel(
    const float* __restrict__ P, const float* __restrict__ st,
    float* __restrict__ out2)
{
    const int bq = blockIdx.x;                   // b*L + q
    const int b = bq >> 11, q = bq & (L_ - 1);
    const float* base = P + (size_t)bq * NH * L_;
    const int t = threadIdx.x;
    float macc[8];
    #pragma unroll
    for (int i = 0; i < 8; i++) macc[i] = 0.0f;

    for (int h = 0; h < NH; h++) {
        size_t si = ((size_t)(b * NH + h) * L_ + q) * 2;
        float2 mz = *reinterpret_cast<const float2*>(&st[si]);
        const float* p = base + (size_t)h * L_;
        #pragma unroll
        for (int i = 0; i < 8; i++)
            macc[i] += fast_exp(p[t + i * 256] - mz.x) * mz.y;
    }
    float* o = out2 + (size_t)bq * L_;
    #pragma unroll
    for (int i = 0; i < 8; i++) o[t + i * 256] = macc[i] * (1.0f / NH);
}

// ===== context: softmax fused into PV GEMM; A=Vt(64 x k), B=exp(P) rows(q) =====
__global__ __launch_bounds__(256, 4) void context_kernel(
    const float* __restrict__ P, const float* __restrict__ Vt,
    const float* __restrict__ st, float* __restrict__ out1)
{
    __shared__ float buf[128 * 68];                      // 34.8 KB, reused
    float (*As)[36] = reinterpret_cast<float(*)[36]>(buf);            // 64 x 36
    float (*Bs)[36] = reinterpret_cast<float(*)[36]>(buf + 64 * 36);  // 128 x 36
    float (*Ss)[68] = reinterpret_cast<float(*)[68]>(buf);            // 128 x 68 (after)
    __shared__ float Ms[128], iZs[128];

    const int bh = blockIdx.z;
    const int b  = bh >> 4, h = bh & 15;
    const int q0 = blockIdx.x * 128;
    const int t = threadIdx.x, lane = t & 31, wid = t >> 5;
    const int wm = wid >> 2, wn = wid & 3;      // 2(m=d) x 4(n=q) warps, warp 32x32
    const int g = lane >> 2, tig = lane & 3;

    const float* Abase = Vt + (size_t)bh * DK * L_;
    const float* Bbase = P + ((size_t)(b * L_ + q0) * NH + h) * L_;
    const size_t bstride = (size_t)NH * L_;

    if (t < 128) {
        float2 mz = *reinterpret_cast<const float2*>(&st[((size_t)bh * L_ + q0 + t) * 2]);
        Ms[t] = mz.x; iZs[t] = mz.y;
    }
    __syncthreads();

    float acc[2][4][4];
    #pragma unroll
    for (int mt = 0; mt < 2; mt++)
        #pragma unroll
        for (int nt = 0; nt < 4; nt++)
            #pragma unroll
            for (int i = 0; i < 4; i++) acc[mt][nt][i] = 0.0f;

    for (int k0 = 0; k0 < L_; k0 += 32) {
        #pragma unroll
        for (int it = 0; it < 2; it++) {
            int r = (t >> 3) + it * 32, c4 = (t & 7) * 4;
            float4 a = *reinterpret_cast<const float4*>(&Abase[(size_t)r * L_ + k0 + c4]);
            a.x = tf32f(a.x); a.y = tf32f(a.y); a.z = tf32f(a.z); a.w = tf32f(a.w);
            *reinterpret_cast<float4*>(&As[r][c4]) = a;
        }
        #pragma unroll
        for (int it = 0; it < 4; it++) {
            int r = (t >> 3) + it * 32, c4 = (t & 7) * 4;
            float4 p4 = *reinterpret_cast<const float4*>(&Bbase[(size_t)r * bstride + k0 + c4]);
            float M = Ms[r], iZ = iZs[r];
            p4.x = tf32f(fast_exp(p4.x - M) * iZ);
            p4.y = tf32f(fast_exp(p4.y - M) * iZ);
            p4.z = tf32f(fast_exp(p4.z - M) * iZ);
            p4.w = tf32f(fast_exp(p4.w - M) * iZ);
            *reinterpret_cast<float4*>(&Bs[r][c4]) = p4;
        }
        __syncthreads();
        #pragma unroll
        for (int kk = 0; kk < 32; kk += 8) {
            uint32_t af[2][4], bf[4][2];
            #pragma unroll
            for (int mt = 0; mt < 2; mt++) {
                int rm = wm * 32 + mt * 16 + g;
                af[mt][0] = __float_as_uint(As[rm][kk + tig]);
                af[mt][1] = __float_as_uint(As[rm + 8][kk + tig]);
                af[mt][2] = __float_as_uint(As[rm][kk + tig + 4]);
                af[mt][3] = __float_as_uint(As[rm + 8][kk + tig + 4]);
            }
            #pragma unroll
            for (int nt = 0; nt < 4; nt++) {
                int rn = wn * 32 + nt * 8 + g;
                bf[nt][0] = __float_as_uint(Bs[rn][kk + tig]);
                bf[nt][1] = __float_as_uint(Bs[rn][kk + tig + 4]);
            }
            #pragma unroll
            for (int mt = 0; mt < 2; mt++)
                #pragma unroll
                for (int nt = 0; nt < 4; nt++)
                    mma8(acc[mt][nt], af[mt], bf[nt]);
        }
        __syncthreads();
    }

    // transpose through smem: Ss[q][d], then coalesced store
    #pragma unroll
    for (int mt = 0; mt < 2; mt++) {
        #pragma unroll
        for (int nt = 0; nt < 4; nt++) {
            int d0 = wm * 32 + mt * 16 + g;
            int qq = wn * 32 + nt * 8 + tig * 2;
            Ss[qq][d0]         = acc[mt][nt][0];
            Ss[qq + 1][d0]     = acc[mt][nt][1];
            Ss[qq][d0 + 8]     = acc[mt][nt][2];
            Ss[qq + 1][d0 + 8] = acc[mt][nt][3];
        }
    }
    __syncthreads();

    {
        int qq = t >> 1;
        int d0 = (t & 1) * 32;
        float* orow = out1 + ((size_t)(b * L_) + q0 + qq) * D_ + h * DK + d0;
        #pragma unroll
        for (int j = 0; j < 8; j++) {
            *reinterpret_cast<float4*>(&orow[j * 4]) =
                *reinterpret_cast<float4*>(&Ss[qq][d0 + j * 4]);
        }
    }
}

// ---------------- LayerNorm rows of X -> out0 ----------------
__global__ __launch_bounds__(256) void ln_kernel(
    const float* __restrict__ X, const float* __restrict__ gamma,
    const float* __restrict__ beta, float* __restrict__ out0)
{
    const int m = blockIdx.x;
    const int t = threadIdx.x;
    const float4* x4 = reinterpret_cast<const float4*>(X + (size_t)m * D_);
    float4 v = x4[t];
    float s = v.x + v.y + v.z + v.w;
    s = blockSum256(s);
    float mu = s * (1.0f / D_);
    float dx = v.x - mu, dy = v.y - mu, dz = v.z - mu, dw = v.w - mu;
    float ss = dx * dx + dy * dy + dz * dz + dw * dw;
    ss = blockSum256(ss);
    float r = rsqrtf(ss * (1.0f / D_) + 1e-5f);
    const float4 g  = reinterpret_cast<const float4*>(gamma)[t];
    const float4 be = reinterpret_cast<const float4*>(beta)[t];
    float4 o;
    o.x = dx * r * g.x + be.x;
    o.y = dy * r * g.y + be.y;
    o.z = dz * r * g.z + be.z;
    o.w = dw * r * g.w + be.w;
    reinterpret_cast<float4*>(out0 + (size_t)m * D_)[t] = o;
}

// ---------------- launch ----------------
extern "C" void kernel_launch(void* const* d_in, const int* in_sizes, int n_in,
                              void* d_out, int out_size)
{
    const float* Q     = (const float*)d_in[0];
    const float* K     = (const float*)d_in[1];
    const float* V     = (const float*)d_in[2];
    const int*   mask  = (const int*)d_in[3];
    const float* Wq    = (const float*)d_in[4];
    const float* bq    = (const float*)d_in[5];
    const float* Wk    = (const float*)d_in[6];
    const float* bk    = (const float*)d_in[7];
    const float* Wv    = (const float*)d_in[8];
    const float* bv    = (const float*)d_in[9];
    const float* Wo    = (const float*)d_in[10];
    const float* bo    = (const float*)d_in[11];
    const float* gamma = (const float*)d_in[12];
    const float* beta  = (const float*)d_in[13];

    float* out0 = (float*)d_out;                       // output  [B,L,D]
    float* out1 = out0 + (size_t)ML_ * D_;             // context [B,L,D]
    float* out2 = out1 + (size_t)ML_ * D_;             // attn_mean [B,L,L]

    void *pQh, *pKh, *pVt, *pP, *pPS, *pST, *pX;
    cudaGetSymbolAddress(&pQh, g_Qh);
    cudaGetSymbolAddress(&pKh, g_Kh);
    cudaGetSymbolAddress(&pVt, g_Vt);
    cudaGetSymbolAddress(&pP,  g_P);
    cudaGetSymbolAddress(&pPS, g_PS);
    cudaGetSymbolAddress(&pST, g_ST);
    cudaGetSymbolAddress(&pX,  g_X);

    // 1) QKV projections (tensor core); V transposed
    qkv_gemm<<<dim3(8, 64, 3), 256>>>(Q, K, V, Wq, Wk, Wv, bq, bk, bv,
                                      (float*)pQh, (float*)pKh, (float*)pVt);

    // 2) raw masked scores + per-tile partial stats
    scores_kernel<<<dim3(16, 16, BH_), 256>>>((const float*)pQh, (const float*)pKh,
                                              mask, (float*)pP, (float*)pPS, 0.125f);

    // 3) reduce partial stats -> (M, 1/Z) per row
    stats_reduce<<<BH_ * L_ / 256, 256>>>((const float*)pPS, (float*)pST);

    // 4) attn_mean from raw P + stats
    mean_kernel<<<B_ * L_, 256>>>((const float*)pP, (const float*)pST, out2);

    // 5) context = softmax(P) @ V (softmax fused into staging) -> out1
    context_kernel<<<dim3(16, 1, BH_), 256>>>((const float*)pP, (const float*)pVt,
                                              (const float*)pST, out1);

    // 6) output projection + bias + residual -> X
    out_gemm<<<dim3(8, 64), 256>>>(out1, Wo, bo, Q, (float*)pX);

    // 7) LayerNorm -> out0
    ln_kernel<<<ML_, 256>>>((const float*)pX, gamma, beta, out0);
}

// round 8
// speedup vs baseline: 2.0923x; 1.0001x over previous
#include <cuda_runtime.h>
#include <stdint.h>
#include <math.h>

// Problem constants
#define B_   4
#define L_   2048
#define D_   1024
#define NH   16
#define DK   64
#define BH_  (B_*NH)     // 64
#define ML_  (B_*L_)     // 8192

// ---------------- scratch (static device arrays; no allocation allowed) ----------
__device__ float g_Qh[(size_t)BH_*L_*DK];                 // [bh][l][dk]
__device__ float g_Kh[(size_t)BH_*L_*DK];                 // [bh][l][dk]
__device__ float g_Vt[(size_t)BH_*DK*L_];                 // [bh][d][l]  (transposed V)
__device__ float g_P [(size_t)B_*L_*NH*L_];               // 1.07 GB raw masked scores [b][q][h][k]
__device__ float g_PS[(size_t)BH_*L_*16*2];               // partial stats [bh][q][tile16][max,sumexp]
__device__ float g_ST[(size_t)BH_*L_*2];                  // final stats [bh][q][M, 1/Z]
__device__ float g_X [(size_t)ML_*D_];                    // pre-LN activations

// ---------------- helpers ----------------
__device__ __forceinline__ float blockSum256(float v) {
    __shared__ float s[8];
    #pragma unroll
    for (int o = 16; o; o >>= 1) v += __shfl_xor_sync(0xffffffffu, v, o);
    if ((threadIdx.x & 31) == 0) s[threadIdx.x >> 5] = v;
    __syncthreads();
    if (threadIdx.x < 32) {
        float w = (threadIdx.x < 8) ? s[threadIdx.x] : 0.0f;
        #pragma unroll
        for (int o = 4; o; o >>= 1) w += __shfl_xor_sync(0xffffffffu, w, o);
        if (threadIdx.x == 0) s[0] = w;
    }
    __syncthreads();
    float r = s[0];
    __syncthreads();
    return r;
}

// FFMA-only exp for x <= 0. |rel err| < 3e-6.
__device__ __forceinline__ float fast_exp(float x) {
    x = fmaxf(x, -80.0f);
    float y = x * 1.4426950408889634f;
    float t = y + 12582912.0f;
    int   n = __float_as_int(t) - 0x4B400000;
    float f = y - (t - 12582912.0f);
    float u = f * 0.6931471805599453f;
    float p = 1.0f + u * (1.0f + u * (0.5f + u * (0.166666667f + u * (0.0416666667f + u * 0.008333333f))));
    return p * __int_as_float((n + 127) << 23);
}

// tf32 round-to-nearest (stays in a 32-bit float container)
__device__ __forceinline__ float tf32f(float x) {
    uint32_t u;
    asm("cvt.rna.tf32.f32 %0, %1;" : "=r"(u) : "f"(x));
    return __uint_as_float(u);
}

// D += A(16x8,row) * B(8x8,col)   tf32 inputs, f32 accum
__device__ __forceinline__ void mma8(float* d, const uint32_t* a, const uint32_t* b) {
    asm volatile(
        "mma.sync.aligned.m16n8k8.row.col.f32.tf32.tf32.f32 "
        "{%0,%1,%2,%3}, {%4,%5,%6,%7}, {%8,%9}, {%0,%1,%2,%3};"
        : "+f"(d[0]), "+f"(d[1]), "+f"(d[2]), "+f"(d[3])
        : "r"(a[0]), "r"(a[1]), "r"(a[2]), "r"(a[3]), "r"(b[0]), "r"(b[1]));
}

// ============ merged QKV projection (tf32 tensor core) ============
__global__ __launch_bounds__(256) void qkv_gemm(
    const float* __restrict__ Qin, const float* __restrict__ Kin, const float* __restrict__ Vin,
    const float* __restrict__ Wq,  const float* __restrict__ Wk,  const float* __restrict__ Wv,
    const float* __restrict__ bq,  const float* __restrict__ bk,  const float* __restrict__ bv,
    float* __restrict__ Qh, float* __restrict__ Kh, float* __restrict__ Vt)
{
    const int zid = blockIdx.z;
    const float* A    = (zid == 0) ? Qin : (zid == 1) ? Kin : Vin;
    const float* W    = (zid == 0) ? Wq  : (zid == 1) ? Wk  : Wv;
    const float* bias = (zid == 0) ? bq  : (zid == 1) ? bk  : bv;

    __shared__ float As[128][36];
    __shared__ float Bs[128][36];
    const int t = threadIdx.x, lane = t & 31, wid = t >> 5;
    const int wm = wid >> 1, wn = wid & 1;
    const int g = lane >> 2, tig = lane & 3;
    const int m0 = blockIdx.y * 128, n0 = blockIdx.x * 128;

    float acc[2][8][4];
    #pragma unroll
    for (int mt = 0; mt < 2; mt++)
        #pragma unroll
        for (int nt = 0; nt < 8; nt++)
            #pragma unroll
            for (int i = 0; i < 4; i++) acc[mt][nt][i] = 0.0f;

    for (int k0 = 0; k0 < D_; k0 += 32) {
        #pragma unroll
        for (int it = 0; it < 4; it++) {
            int r = (t >> 3) + it * 32, c4 = (t & 7) * 4;
            float4 a = *reinterpret_cast<const float4*>(&A[(size_t)(m0 + r) * D_ + k0 + c4]);
            a.x = tf32f(a.x); a.y = tf32f(a.y); a.z = tf32f(a.z); a.w = tf32f(a.w);
            *reinterpret_cast<float4*>(&As[r][c4]) = a;
            float4 w = *reinterpret_cast<const float4*>(&W[(size_t)(n0 + r) * D_ + k0 + c4]);
            w.x = tf32f(w.x); w.y = tf32f(w.y); w.z = tf32f(w.z); w.w = tf32f(w.w);
            *reinterpret_cast<float4*>(&Bs[r][c4]) = w;
        }
        __syncthreads();
        #pragma unroll
        for (int kk = 0; kk < 32; kk += 8) {
            uint32_t af[2][4], bf[8][2];
            #pragma unroll
            for (int mt = 0; mt < 2; mt++) {
                int rm = wm * 32 + mt * 16 + g;
                af[mt][0] = __float_as_uint(As[rm][kk + tig]);
                af[mt][1] = __float_as_uint(As[rm + 8][kk + tig]);
                af[mt][2] = __float_as_uint(As[rm][kk + tig + 4]);
                af[mt][3] = __float_as_uint(As[rm + 8][kk + tig + 4]);
            }
            #pragma unroll
            for (int nt = 0; nt < 8; nt++) {
                int rn = wn * 64 + nt * 8 + g;
                bf[nt][0] = __float_as_uint(Bs[rn][kk + tig]);
                bf[nt][1] = __float_as_uint(Bs[rn][kk + tig + 4]);
            }
            #pragma unroll
            for (int mt = 0; mt < 2; mt++)
                #pragma unroll
                for (int nt = 0; nt < 8; nt++)
                    mma8(acc[mt][nt], af[mt], bf[nt]);
        }
        __syncthreads();
    }

    #pragma unroll
    for (int mt = 0; mt < 2; mt++) {
        #pragma unroll
        for (int nt = 0; nt < 8; nt++) {
            int n  = n0 + wn * 64 + nt * 8 + tig * 2;
            int h  = n >> 6, d = n & (DK - 1);
            float2 bv2 = *reinterpret_cast<const float2*>(&bias[n]);
            #pragma unroll
            for (int rr = 0; rr < 2; rr++) {
                int m = m0 + wm * 32 + mt * 16 + g + rr * 8;
                int bq_ = m >> 11, l = m & (L_ - 1);
                float v0 = acc[mt][nt][rr * 2 + 0] + bv2.x;
                float v1 = acc[mt][nt][rr * 2 + 1] + bv2.y;
                if (zid < 2) {
                    float* C = (zid == 0) ? Qh : Kh;
                    *reinterpret_cast<float2*>(
                        &C[(((size_t)(bq_ * NH + h)) * L_ + l) * DK + d]) = make_float2(v0, v1);
                } else {
                    size_t base = ((size_t)(bq_ * NH + h) * DK + d) * L_ + l;
                    Vt[base]      = v0;
                    Vt[base + L_] = v1;
                }
            }
        }
    }
}

// ============ output projection + residual (tf32 tensor core) ============
__global__ __launch_bounds__(256) void out_gemm(
    const float* __restrict__ A, const float* __restrict__ W,
    const float* __restrict__ bias, const float* __restrict__ R,
    float* __restrict__ C)
{
    __shared__ float As[128][36];
    __shared__ float Bs[128][36];
    const int t = threadIdx.x, lane = t & 31, wid = t >> 5;
    const int wm = wid >> 1, wn = wid & 1;
    const int g = lane >> 2, tig = lane & 3;
    const int m0 = blockIdx.y * 128, n0 = blockIdx.x * 128;

    float acc[2][8][4];
    #pragma unroll
    for (int mt = 0; mt < 2; mt++)
        #pragma unroll
        for (int nt = 0; nt < 8; nt++)
            #pragma unroll
            for (int i = 0; i < 4; i++) acc[mt][nt][i] = 0.0f;

    for (int k0 = 0; k0 < D_; k0 += 32) {
        #pragma unroll
        for (int it = 0; it < 4; it++) {
            int r = (t >> 3) + it * 32, c4 = (t & 7) * 4;
            float4 a = *reinterpret_cast<const float4*>(&A[(size_t)(m0 + r) * D_ + k0 + c4]);
            a.x = tf32f(a.x); a.y = tf32f(a.y); a.z = tf32f(a.z); a.w = tf32f(a.w);
            *reinterpret_cast<float4*>(&As[r][c4]) = a;
            float4 w = *reinterpret_cast<const float4*>(&W[(size_t)(n0 + r) * D_ + k0 + c4]);
            w.x = tf32f(w.x); w.y = tf32f(w.y); w.z = tf32f(w.z); w.w = tf32f(w.w);
            *reinterpret_cast<float4*>(&Bs[r][c4]) = w;
        }
        __syncthreads();
        #pragma unroll
        for (int kk = 0; kk < 32; kk += 8) {
            uint32_t af[2][4], bf[8][2];
            #pragma unroll
            for (int mt = 0; mt < 2; mt++) {
                int rm = wm * 32 + mt * 16 + g;
                af[mt][0] = __float_as_uint(As[rm][kk + tig]);
                af[mt][1] = __float_as_uint(As[rm + 8][kk + tig]);
                af[mt][2] = __float_as_uint(As[rm][kk + tig + 4]);
                af[mt][3] = __float_as_uint(As[rm + 8][kk + tig + 4]);
            }
            #pragma unroll
            for (int nt = 0; nt < 8; nt++) {
                int rn = wn * 64 + nt * 8 + g;
                bf[nt][0] = __float_as_uint(Bs[rn][kk + tig]);
                bf[nt][1] = __float_as_uint(Bs[rn][kk + tig + 4]);
            }
            #pragma unroll
            for (int mt = 0; mt < 2; mt++)
                #pragma unroll
                for (int nt = 0; nt < 8; nt++)
                    mma8(acc[mt][nt], af[mt], bf[nt]);
        }
        __syncthreads();
    }

    #pragma unroll
    for (int mt = 0; mt < 2; mt++) {
        #pragma unroll
        for (int nt = 0; nt < 8; nt++) {
            int n = n0 + wn * 64 + nt * 8 + tig * 2;
            float2 bv2 = *reinterpret_cast<const float2*>(&bias[n]);
            #pragma unroll
            for (int rr = 0; rr < 2; rr++) {
                int m = m0 + wm * 32 + mt * 16 + g + rr * 8;
                size_t idx = (size_t)m * D_ + n;
                float2 r2 = *reinterpret_cast<const float2*>(&R[idx]);
                *reinterpret_cast<float2*>(&C[idx]) = make_float2(
                    acc[mt][nt][rr * 2 + 0] + bv2.x + r2.x,
                    acc[mt][nt][rr * 2 + 1] + bv2.y + r2.y);
            }
        }
    }
}

// ============ scores (tf32) + per-tile softmax partial stats ============
// writes raw masked scores to P[b][q][h][k] and (max, sumexp) per (row, 128-col tile)
__global__ __launch_bounds__(256) void scores_kernel(
    const float* __restrict__ Qh, const float* __restrict__ Kh,
    const int* __restrict__ mask, float* __restrict__ P,
    float* __restrict__ pstats, float scale)
{
    __shared__ float As[128][36];
    __shared__ float Bs[128][36];
    __shared__ float rmax[128][2];
    __shared__ float rsum[128][2];
    const int bh = blockIdx.z;
    const int b  = bh >> 4, h = bh & 15;
    const float* Aq = Qh + (size_t)bh * L_ * DK;
    const float* Ak = Kh + (size_t)bh * L_ * DK;
    const int q0 = blockIdx.y * 128;
    const int c0 = blockIdx.x * 128;
    const int t = threadIdx.x, lane = t & 31, wid = t >> 5;
    const int wm = wid >> 1, wn = wid & 1;
    const int g = lane >> 2, tig = lane & 3;

    float acc[2][8][4];
    #pragma unroll
    for (int mt = 0; mt < 2; mt++)
        #pragma unroll
        for (int nt = 0; nt < 8; nt++)
            #pragma unroll
            for (int i = 0; i < 4; i++) acc[mt][nt][i] = 0.0f;

    #pragma unroll
    for (int k0 = 0; k0 < DK; k0 += 32) {
        #pragma unroll
        for (int it = 0; it < 4; it++) {
            int r = (t >> 3) + it * 32, c4 = (t & 7) * 4;
            float4 a = *reinterpret_cast<const float4*>(&Aq[(size_t)(q0 + r) * DK + k0 + c4]);
            a.x = tf32f(a.x); a.y = tf32f(a.y); a.z = tf32f(a.z); a.w = tf32f(a.w);
            *reinterpret_cast<float4*>(&As[r][c4]) = a;
            float4 w = *reinterpret_cast<const float4*>(&Ak[(size_t)(c0 + r) * DK + k0 + c4]);
            w.x = tf32f(w.x); w.y = tf32f(w.y); w.z = tf32f(w.z); w.w = tf32f(w.w);
            *reinterpret_cast<float4*>(&Bs[r][c4]) = w;
        }
        __syncthreads();
        #pragma unroll
        for (int kk = 0; kk < 32; kk += 8) {
            uint32_t af[2][4], bf[8][2];
            #pragma unroll
            for (int mt = 0; mt < 2; mt++) {
                int rm = wm * 32 + mt * 16 + g;
                af[mt][0] = __float_as_uint(As[rm][kk + tig]);
                af[mt][1] = __float_as_uint(As[rm + 8][kk + tig]);
                af[mt][2] = __float_as_uint(As[rm][kk + tig + 4]);
                af[mt][3] = __float_as_uint(As[rm + 8][kk + tig + 4]);
            }
            #pragma unroll
            for (int nt = 0; nt < 8; nt++) {
                int rn = wn * 64 + nt * 8 + g;
                bf[nt][0] = __float_as_uint(Bs[rn][kk + tig]);
                bf[nt][1] = __float_as_uint(Bs[rn][kk + tig + 4]);
            }
            #pragma unroll
            for (int mt = 0; mt < 2; mt++)
                #pragma unroll
                for (int nt = 0; nt < 8; nt++)
                    mma8(acc[mt][nt], af[mt], bf[nt]);
        }
        __syncthreads();
    }

    // scale + mask in-register, write raw P
    #pragma unroll
    for (int mt = 0; mt < 2; mt++) {
        #pragma unroll
        for (int nt = 0; nt < 8; nt++) {
            int c = c0 + wn * 64 + nt * 8 + tig * 2;
            #pragma unroll
            for (int rr = 0; rr < 2; rr++) {
                int q = q0 + wm * 32 + mt * 16 + g + rr * 8;
                const int* mrow = mask + (size_t)b * L_ * L_ + (size_t)q * L_;
                int2 m2 = *reinterpret_cast<const int2*>(&mrow[c]);
                float v0 = acc[mt][nt][rr * 2 + 0] * scale;
                float v1 = acc[mt][nt][rr * 2 + 1] * scale;
                if (m2.x) v0 = -1e9f;
                if (m2.y) v1 = -1e9f;
                acc[mt][nt][rr * 2 + 0] = v0;
                acc[mt][nt][rr * 2 + 1] = v1;
                float* prow = P + (((size_t)(b * L_ + q)) * NH + h) * L_;
                *reinterpret_cast<float2*>(&prow[c]) = make_float2(v0, v1);
            }
        }
    }

    // phase 1: per-row tile max (this block's 128 cols)
    #pragma unroll
    for (int mt = 0; mt < 2; mt++) {
        #pragma unroll
        for (int rr = 0; rr < 2; rr++) {
            float m = -3.4e38f;
            #pragma unroll
            for (int nt = 0; nt < 8; nt++) {
                m = fmaxf(m, acc[mt][nt][rr * 2 + 0]);
                m = fmaxf(m, acc[mt][nt][rr * 2 + 1]);
            }
            m = fmaxf(m, __shfl_xor_sync(0xffffffffu, m, 1));
            m = fmaxf(m, __shfl_xor_sync(0xffffffffu, m, 2));
            int rl = wm * 32 + mt * 16 + g + rr * 8;
            if (tig == 0) rmax[rl][wn] = m;
        }
    }
    __syncthreads();

    // phase 2: per-row tile sumexp with tile max
    #pragma unroll
    for (int mt = 0; mt < 2; mt++) {
        #pragma unroll
        for (int rr = 0; rr < 2; rr++) {
            int rl = wm * 32 + mt * 16 + g + rr * 8;
            float M = fmaxf(rmax[rl][0], rmax[rl][1]);
            float s = 0.0f;
            #pragma unroll
            for (int nt = 0; nt < 8; nt++) {
                s += fast_exp(acc[mt][nt][rr * 2 + 0] - M);
                s += fast_exp(acc[mt][nt][rr * 2 + 1] - M);
            }
            s += __shfl_xor_sync(0xffffffffu, s, 1);
            s += __shfl_xor_sync(0xffffffffu, s, 2);
            if (tig == 0) rsum[rl][wn] = s;
        }
    }
    __syncthreads();

    // phase 3: one writer per row
    if (wn == 0 && tig == 0) {
        #pragma unroll
        for (int mt = 0; mt < 2; mt++) {
            #pragma unroll
            for (int rr = 0; rr < 2; rr++) {
                int rl = wm * 32 + mt * 16 + g + rr * 8;
                int q = q0 + rl;
                float M = fmaxf(rmax[rl][0], rmax[rl][1]);
                float S = rsum[rl][0] + rsum[rl][1];
                size_t si = (((size_t)bh * L_ + q) * 16 + blockIdx.x) * 2;
                *reinterpret_cast<float2*>(&pstats[si]) = make_float2(M, S);
            }
        }
    }
}

// ============ reduce partial stats -> per-row (M, 1/Z) ============
__global__ __launch_bounds__(256) void stats_reduce(
    const float* __restrict__ pstats, float* __restrict__ st)
{
    int idx = blockIdx.x * 256 + threadIdx.x;     // bh*L + q, total 131072
    const float4* p = reinterpret_cast<const float4*>(pstats + (size_t)idx * 32);
    float mx[16], sm[16];
    #pragma unroll
    for (int i = 0; i < 8; i++) {
        float4 v = p[i];
        mx[i * 2] = v.x; sm[i * 2] = v.y;
        mx[i * 2 + 1] = v.z; sm[i * 2 + 1] = v.w;
    }
    float M = -3.4e38f;
    #pragma unroll
    for (int i = 0; i < 16; i++) M = fmaxf(M, mx[i]);
    float Z = 0.0f;
    #pragma unroll
    for (int i = 0; i < 16; i++) Z += sm[i] * fast_exp(mx[i] - M);
    *reinterpret_cast<float2*>(&st[(size_t)idx * 2]) = make_float2(M, 1.0f / Z);
}

// ============ attn_mean from raw P + stats ============
__global__ __launch_bounds__(256) void mean_kernel(
    const float* __restrict__ P, const float* __restrict__ st,
    float* __restrict__ out2)
{
    const int bq = blockIdx.x;                   // b*L + q
    const int b = bq >> 11, q = bq & (L_ - 1);
    const float* base = P + (size_t)bq * NH * L_;
    const int t = threadIdx.x;
    float macc[8];
    #pragma unroll
    for (int i = 0; i < 8; i++) macc[i] = 0.0f;

    for (int h = 0; h < NH; h++) {
        size_t si = ((size_t)(b * NH + h) * L_ + q) * 2;
        float2 mz = *reinterpret_cast<const float2*>(&st[si]);
        const float* p = base + (size_t)h * L_;
        #pragma unroll
        for (int i = 0; i < 8; i++)
            macc[i] += fast_exp(p[t + i * 256] - mz.x) * mz.y;
    }
    float* o = out2 + (size_t)bq * L_;
    #pragma unroll
    for (int i = 0; i < 8; i++) o[t + i * 256] = macc[i] * (1.0f / NH);
}

// ===== context: softmax fused into PV GEMM; A=Vt(64 x k), B=exp(P) rows(q) =====
__global__ __launch_bounds__(256, 4) void context_kernel(
    const float* __restrict__ P, const float* __restrict__ Vt,
    const float* __restrict__ st, float* __restrict__ out1)
{
    __shared__ float buf[128 * 68];                      // 34.8 KB, reused
    float (*As)[36] = reinterpret_cast<float(*)[36]>(buf);            // 64 x 36
    float (*Bs)[36] = reinterpret_cast<float(*)[36]>(buf + 64 * 36);  // 128 x 36
    float (*Ss)[68] = reinterpret_cast<float(*)[68]>(buf);            // 128 x 68 (after)
    __shared__ float Ms[128], iZs[128];

    const int bh = blockIdx.z;
    const int b  = bh >> 4, h = bh & 15;
    const int q0 = blockIdx.x * 128;
    const int t = threadIdx.x, lane = t & 31, wid = t >> 5;
    const int wm = wid >> 2, wn = wid & 3;      // 2(m=d) x 4(n=q) warps, warp 32x32
    const int g = lane >> 2, tig = lane & 3;

    const float* Abase = Vt + (size_t)bh * DK * L_;
    const float* Bbase = P + ((size_t)(b * L_ + q0) * NH + h) * L_;
    const size_t bstride = (size_t)NH * L_;

    if (t < 128) {
        float2 mz = *reinterpret_cast<const float2*>(&st[((size_t)bh * L_ + q0 + t) * 2]);
        Ms[t] = mz.x; iZs[t] = mz.y;
    }
    __syncthreads();

    float acc[2][4][4];
    #pragma unroll
    for (int mt = 0; mt < 2; mt++)
        #pragma unroll
        for (int nt = 0; nt < 4; nt++)
            #pragma unroll
            for (int i = 0; i < 4; i++) acc[mt][nt][i] = 0.0f;

    for (int k0 = 0; k0 < L_; k0 += 32) {
        #pragma unroll
        for (int it = 0; it < 2; it++) {
            int r = (t >> 3) + it * 32, c4 = (t & 7) * 4;
            float4 a = *reinterpret_cast<const float4*>(&Abase[(size_t)r * L_ + k0 + c4]);
            a.x = tf32f(a.x); a.y = tf32f(a.y); a.z = tf32f(a.z); a.w = tf32f(a.w);
            *reinterpret_cast<float4*>(&As[r][c4]) = a;
        }
        #pragma unroll
        for (int it = 0; it < 4; it++) {
            int r = (t >> 3) + it * 32, c4 = (t & 7) * 4;
            float4 p4 = *reinterpret_cast<const float4*>(&Bbase[(size_t)r * bstride + k0 + c4]);
            float M = Ms[r], iZ = iZs[r];
            p4.x = tf32f(fast_exp(p4.x - M) * iZ);
            p4.y = tf32f(fast_exp(p4.y - M) * iZ);
            p4.z = tf32f(fast_exp(p4.z - M) * iZ);
            p4.w = tf32f(fast_exp(p4.w - M) * iZ);
            *reinterpret_cast<float4*>(&Bs[r][c4]) = p4;
        }
        __syncthreads();
        #pragma unroll
        for (int kk = 0; kk < 32; kk += 8) {
            uint32_t af[2][4], bf[4][2];
            #pragma unroll
            for (int mt = 0; mt < 2; mt++) {
                int rm = wm * 32 + mt * 16 + g;
                af[mt][0] = __float_as_uint(As[rm][kk + tig]);
                af[mt][1] = __float_as_uint(As[rm + 8][kk + tig]);
                af[mt][2] = __float_as_uint(As[rm][kk + tig + 4]);
                af[mt][3] = __float_as_uint(As[rm + 8][kk + tig + 4]);
            }
            #pragma unroll
            for (int nt = 0; nt < 4; nt++) {
                int rn = wn * 32 + nt * 8 + g;
                bf[nt][0] = __float_as_uint(Bs[rn][kk + tig]);
                bf[nt][1] = __float_as_uint(Bs[rn][kk + tig + 4]);
            }
            #pragma unroll
            for (int mt = 0; mt < 2; mt++)
                #pragma unroll
                for (int nt = 0; nt < 4; nt++)
                    mma8(acc[mt][nt], af[mt], bf[nt]);
        }
        __syncthreads();
    }

    // transpose through smem: Ss[q][d], then coalesced store
    #pragma unroll
    for (int mt = 0; mt < 2; mt++) {
        #pragma unroll
        for (int nt = 0; nt < 4; nt++) {
            int d0 = wm * 32 + mt * 16 + g;
            int qq = wn * 32 + nt * 8 + tig * 2;
            Ss[qq][d0]         = acc[mt][nt][0];
            Ss[qq + 1][d0]     = acc[mt][nt][1];
            Ss[qq][d0 + 8]     = acc[mt][nt][2];
            Ss[qq + 1][d0 + 8] = acc[mt][nt][3];
        }
    }
    __syncthreads();

    {
        int qq = t >> 1;
        int d0 = (t & 1) * 32;
        float* orow = out1 + ((size_t)(b * L_) + q0 + qq) * D_ + h * DK + d0;
        #pragma unroll
        for (int j = 0; j < 8; j++) {
            *reinterpret_cast<float4*>(&orow[j * 4]) =
                *reinterpret_cast<float4*>(&Ss[qq][d0 + j * 4]);
        }
    }
}

// ---------------- LayerNorm rows of X -> out0 ----------------
__global__ __launch_bounds__(256) void ln_kernel(
    const float* __restrict__ X, const float* __restrict__ gamma,
    const float* __restrict__ beta, float* __restrict__ out0)
{
    const int m = blockIdx.x;
    const int t = threadIdx.x;
    const float4* x4 = reinterpret_cast<const float4*>(X + (size_t)m * D_);
    float4 v = x4[t];
    float s = v.x + v.y + v.z + v.w;
    s = blockSum256(s);
    float mu = s * (1.0f / D_);
    float dx = v.x - mu, dy = v.y - mu, dz = v.z - mu, dw = v.w - mu;
    float ss = dx * dx + dy * dy + dz * dz + dw * dw;
    ss = blockSum256(ss);
    float r = rsqrtf(ss * (1.0f / D_) + 1e-5f);
    const float4 g  = reinterpret_cast<const float4*>(gamma)[t];
    const float4 be = reinterpret_cast<const float4*>(beta)[t];
    float4 o;
    o.x = dx * r * g.x + be.x;
    o.y = dy * r * g.y + be.y;
    o.z = dz * r * g.z + be.z;
    o.w = dw * r * g.w + be.w;
    reinterpret_cast<float4*>(out0 + (size_t)m * D_)[t] = o;
}

// ---------------- launch ----------------
extern "C" void kernel_launch(void* const* d_in, const int* in_sizes, int n_in,
                              void* d_out, int out_size)
{
    const float* Q     = (const float*)d_in[0];
    const float* K     = (const float*)d_in[1];
    const float* V     = (const float*)d_in[2];
    const int*   mask  = (const int*)d_in[3];
    const float* Wq    = (const float*)d_in[4];
    const float* bq    = (const float*)d_in[5];
    const float* Wk    = (const float*)d_in[6];
    const float* bk    = (const float*)d_in[7];
    const float* Wv    = (const float*)d_in[8];
    const float* bv    = (const float*)d_in[9];
    const float* Wo    = (const float*)d_in[10];
    const float* bo    = (const float*)d_in[11];
    const float* gamma = (const float*)d_in[12];
    const float* beta  = (const float*)d_in[13];

    float* out0 = (float*)d_out;                       // output  [B,L,D]
    float* out1 = out0 + (size_t)ML_ * D_;             // context [B,L,D]
    float* out2 = out1 + (size_t)ML_ * D_;             // attn_mean [B,L,L]

    void *pQh, *pKh, *pVt, *pP, *pPS, *pST, *pX;
    cudaGetSymbolAddress(&pQh, g_Qh);
    cudaGetSymbolAddress(&pKh, g_Kh);
    cudaGetSymbolAddress(&pVt, g_Vt);
    cudaGetSymbolAddress(&pP,  g_P);
    cudaGetSymbolAddress(&pPS, g_PS);
    cudaGetSymbolAddress(&pST, g_ST);
    cudaGetSymbolAddress(&pX,  g_X);

    // 1) QKV projections (tensor core); V transposed
    qkv_gemm<<<dim3(8, 64, 3), 256>>>(Q, K, V, Wq, Wk, Wv, bq, bk, bv,
                                      (float*)pQh, (float*)pKh, (float*)pVt);

    // 2) raw masked scores + per-tile partial stats
    scores_kernel<<<dim3(16, 16, BH_), 256>>>((const float*)pQh, (const float*)pKh,
                                              mask, (float*)pP, (float*)pPS, 0.125f);

    // 3) reduce partial stats -> (M, 1/Z) per row
    stats_reduce<<<BH_ * L_ / 256, 256>>>((const float*)pPS, (float*)pST);

    // 4) attn_mean from raw P + stats
    mean_kernel<<<B_ * L_, 256>>>((const float*)pP, (const float*)pST, out2);

    // 5) context = softmax(P) @ V (softmax fused into staging) -> out1
    context_kernel<<<dim3(16, 1, BH_), 256>>>((const float*)pP, (const float*)pVt,
                                              (const float*)pST, out1);

    // 6) output projection + bias + residual -> X
    out_gemm<<<dim3(8, 64), 256>>>(out1, Wo, bo, Q, (float*)pX);

    // 7) LayerNorm -> out0
    ln_kernel<<<ML_, 256>>>((const float*)pX, gamma, beta, out0);
}